// round 1
// baseline (speedup 1.0000x reference)
#include <cuda_runtime.h>
#include <cuda_bf16.h>
#include <math.h>

// ---------------- problem constants ----------------
#define BSZ   2
#define SEQ   2048
#define DMODEL 1024
#define NHEADS 16
#define HDIM   64
#define FFDIM  4096
#define MROWS (BSZ*SEQ)          // 4096
#define LN_EPS 1e-5f

// ---------------- scratch (device globals; no allocs) ----------------
__device__ float g_xn [MROWS*DMODEL];
__device__ float g_q  [MROWS*DMODEL];
__device__ float g_k  [MROWS*DMODEL];
__device__ float g_v  [MROWS*DMODEL];
__device__ float g_ctx[MROWS*DMODEL];
__device__ float g_x2 [MROWS*DMODEL];
__device__ float g_h  [MROWS*FFDIM];

// ---------------- LayerNorm (one block per row of 1024) ----------------
__global__ __launch_bounds__(256) void ln_kernel(const float* __restrict__ x,
                                                 const float* __restrict__ g,
                                                 const float* __restrict__ b,
                                                 float* __restrict__ out) {
    int row = blockIdx.x;
    int t   = threadIdx.x;
    const float4 v = ((const float4*)(x + (size_t)row * DMODEL))[t];
    float s  = v.x + v.y + v.z + v.w;
    float ss = v.x*v.x + v.y*v.y + v.z*v.z + v.w*v.w;
    #pragma unroll
    for (int o = 16; o; o >>= 1) {
        s  += __shfl_xor_sync(0xffffffffu, s,  o);
        ss += __shfl_xor_sync(0xffffffffu, ss, o);
    }
    __shared__ float rs[8], rss[8];
    if ((t & 31) == 0) { rs[t >> 5] = s; rss[t >> 5] = ss; }
    __syncthreads();
    float S = 0.f, SS = 0.f;
    #pragma unroll
    for (int i = 0; i < 8; i++) { S += rs[i]; SS += rss[i]; }
    float mean = S * (1.f / DMODEL);
    float var  = SS * (1.f / DMODEL) - mean * mean;
    float rstd = rsqrtf(var + LN_EPS);
    const float4 gv = ((const float4*)g)[t];
    const float4 bv = ((const float4*)b)[t];
    float4 o4;
    o4.x = (v.x - mean) * rstd * gv.x + bv.x;
    o4.y = (v.y - mean) * rstd * gv.y + bv.y;
    o4.z = (v.z - mean) * rstd * gv.z + bv.z;
    o4.w = (v.w - mean) * rstd * gv.w + bv.w;
    ((float4*)(out + (size_t)row * DMODEL))[t] = o4;
}

// ---------------- tiled fp32 GEMM:  C[M,N] = A[M,K] @ W[N,K]^T + bias ----------------
// epi: 0 = bias only, 1 = bias+GELU(exact erf), 2 = bias + residual R[M,N]
#define BM 128
#define BN 128
#define BK 16

__global__ __launch_bounds__(256) void gemm_nt(const float* __restrict__ A,
                                               const float* __restrict__ W,
                                               const float* __restrict__ bias,
                                               const float* __restrict__ R,
                                               float* __restrict__ C,
                                               int M, int N, int K, int epi) {
    __shared__ float As[BK][BM];
    __shared__ float Bs[BK][BN];
    const int tid = threadIdx.x;
    const int bm  = blockIdx.y * BM;
    const int bn  = blockIdx.x * BN;
    const int tx  = tid & 15;
    const int ty  = tid >> 4;

    float acc[8][8];
    #pragma unroll
    for (int i = 0; i < 8; i++)
        #pragma unroll
        for (int j = 0; j < 8; j++) acc[i][j] = 0.f;

    for (int k0 = 0; k0 < K; k0 += BK) {
        #pragma unroll
        for (int i = 0; i < 2; i++) {
            int f  = tid * 2 + i;
            int r  = f >> 2;
            int kq = f & 3;
            const float4 av = *(const float4*)&A[(size_t)(bm + r) * K + k0 + kq * 4];
            As[kq*4+0][r] = av.x; As[kq*4+1][r] = av.y;
            As[kq*4+2][r] = av.z; As[kq*4+3][r] = av.w;
            const float4 wv = *(const float4*)&W[(size_t)(bn + r) * K + k0 + kq * 4];
            Bs[kq*4+0][r] = wv.x; Bs[kq*4+1][r] = wv.y;
            Bs[kq*4+2][r] = wv.z; Bs[kq*4+3][r] = wv.w;
        }
        __syncthreads();
        #pragma unroll
        for (int kk = 0; kk < BK; kk++) {
            float a[8], bb[8];
            *(float4*)&a[0]  = *(const float4*)&As[kk][ty * 8];
            *(float4*)&a[4]  = *(const float4*)&As[kk][ty * 8 + 4];
            *(float4*)&bb[0] = *(const float4*)&Bs[kk][tx * 8];
            *(float4*)&bb[4] = *(const float4*)&Bs[kk][tx * 8 + 4];
            #pragma unroll
            for (int i = 0; i < 8; i++)
                #pragma unroll
                for (int j = 0; j < 8; j++)
                    acc[i][j] += a[i] * bb[j];
        }
        __syncthreads();
    }

    // epilogue
    #pragma unroll
    for (int i = 0; i < 8; i++) {
        size_t row = (size_t)(bm + ty * 8 + i);
        float tmp[8];
        #pragma unroll
        for (int j = 0; j < 8; j++) {
            int col  = bn + tx * 8 + j;
            float vv = acc[i][j] + bias[col];
            if (epi == 1) {
                vv = 0.5f * vv * (1.0f + erff(vv * 0.7071067811865475f));
            } else if (epi == 2) {
                vv += R[row * (size_t)N + col];
            }
            tmp[j] = vv;
        }
        float* cp = &C[row * (size_t)N + bn + tx * 8];
        *(float4*)&cp[0] = *(float4*)&tmp[0];
        *(float4*)&cp[4] = *(float4*)&tmp[4];
    }
}

// ---------------- causal flash attention (fp32) ----------------
// block: 512 threads (16 warps), owns 64 query rows; 4 interleaved rows per warp.
// chunk: 64 keys in smem (K^T padded stride 65), online softmax in registers.
#define AQ 64
#define AC 64
#define SK_STRIDE 65
// dynamic smem floats: sK 64*65, sV 64*64, sQ 64*64, sP 64*64
#define SMEM_SK  0
#define SMEM_SV  (AC * SK_STRIDE)
#define SMEM_SQ  (SMEM_SV + AC * HDIM)
#define SMEM_SP  (SMEM_SQ + AQ * HDIM)
#define ATTN_SMEM_FLOATS (SMEM_SP + AQ * AC)

__global__ __launch_bounds__(512) void attn_kernel(const float* __restrict__ Q,
                                                   const float* __restrict__ K,
                                                   const float* __restrict__ V,
                                                   float* __restrict__ O) {
    extern __shared__ float sm[];
    float* sK = sm + SMEM_SK;   // [d][j], stride 65
    float* sV = sm + SMEM_SV;   // [j][d]
    float* sQ = sm + SMEM_SQ;   // [r][d]
    float* sP = sm + SMEM_SP;   // [r][j]

    const int bh = blockIdx.y;          // b*16 + h
    const int b  = bh >> 4;
    const int h  = bh & 15;
    const int q0 = blockIdx.x * AQ;

    const size_t base = ((size_t)b * SEQ) * DMODEL + (size_t)h * HDIM;
    const float* Qb = Q + base + (size_t)q0 * DMODEL;
    const float* Kb = K + base;
    const float* Vb = V + base;
    float*       Ob = O + base + (size_t)q0 * DMODEL;

    const int tid  = threadIdx.x;
    const int w    = tid >> 5;
    const int lane = tid & 31;

    // load Q tile
    for (int idx = tid; idx < AQ * HDIM; idx += 512) {
        int r = idx >> 6, d = idx & 63;
        sQ[r * HDIM + d] = Qb[(size_t)r * DMODEL + d];
    }

    int   rl[4];
    float m[4], l[4], a0[4], a1[4];
    #pragma unroll
    for (int i = 0; i < 4; i++) {
        rl[i] = w + i * 16;
        m[i] = -1e30f; l[i] = 0.f; a0[i] = 0.f; a1[i] = 0.f;
    }
    __syncthreads();

    const int kend = q0 + AQ;   // need keys [0, q0+AQ-1]
    for (int c0 = 0; c0 < kend; c0 += AC) {
        // load K chunk (transposed) + V chunk
        for (int idx = tid; idx < AC * HDIM; idx += 512) {
            int j = idx >> 6, d = idx & 63;
            float kv = Kb[(size_t)(c0 + j) * DMODEL + d];
            sK[d * SK_STRIDE + j] = kv;
            sV[j * HDIM + d]      = Vb[(size_t)(c0 + j) * DMODEL + d];
        }
        __syncthreads();

        // scores: lane owns keys (lane, lane+32)
        float s0[4] = {0,0,0,0}, s1[4] = {0,0,0,0};
        #pragma unroll 8
        for (int d = 0; d < HDIM; d++) {
            float k0v = sK[d * SK_STRIDE + lane];
            float k1v = sK[d * SK_STRIDE + lane + 32];
            #pragma unroll
            for (int i = 0; i < 4; i++) {
                float qd = sQ[rl[i] * HDIM + d];
                s0[i] += qd * k0v;
                s1[i] += qd * k1v;
            }
        }

        // online softmax per row
        #pragma unroll
        for (int i = 0; i < 4; i++) {
            int row = q0 + rl[i];
            float x0 = (c0 + lane      <= row) ? s0[i] * 0.125f : -1e30f;
            float x1 = (c0 + lane + 32 <= row) ? s1[i] * 0.125f : -1e30f;
            float mx = fmaxf(x0, x1);
            #pragma unroll
            for (int o = 16; o; o >>= 1) mx = fmaxf(mx, __shfl_xor_sync(0xffffffffu, mx, o));
            float mn   = fmaxf(m[i], mx);
            float corr = __expf(m[i] - mn);
            float p0   = __expf(x0 - mn);
            float p1   = __expf(x1 - mn);
            float ps   = p0 + p1;
            #pragma unroll
            for (int o = 16; o; o >>= 1) ps += __shfl_xor_sync(0xffffffffu, ps, o);
            l[i]  = l[i] * corr + ps;
            a0[i] *= corr;
            a1[i] *= corr;
            m[i]  = mn;
            sP[rl[i] * AC + lane]      = p0;
            sP[rl[i] * AC + lane + 32] = p1;
        }
        __syncwarp();

        // accumulate: lane owns output dims (lane, lane+32)
        #pragma unroll 4
        for (int j = 0; j < AC; j++) {
            float v0 = sV[j * HDIM + lane];
            float v1 = sV[j * HDIM + lane + 32];
            #pragma unroll
            for (int i = 0; i < 4; i++) {
                float p = sP[rl[i] * AC + j];
                a0[i] += p * v0;
                a1[i] += p * v1;
            }
        }
        __syncthreads();
    }

    #pragma unroll
    for (int i = 0; i < 4; i++) {
        float inv = 1.f / l[i];
        Ob[(size_t)rl[i] * DMODEL + lane]      = a0[i] * inv;
        Ob[(size_t)rl[i] * DMODEL + lane + 32] = a1[i] * inv;
    }
}

// ---------------- launcher ----------------
extern "C" void kernel_launch(void* const* d_in, const int* in_sizes, int n_in,
                              void* d_out, int out_size) {
    const float* x     = (const float*)d_in[0];
    // d_in[1] = attn_mask (causal, known analytically — unused)
    const float* Wq    = (const float*)d_in[2];
    const float* bq    = (const float*)d_in[3];
    const float* Wk    = (const float*)d_in[4];
    const float* bk    = (const float*)d_in[5];
    const float* Wv    = (const float*)d_in[6];
    const float* bv    = (const float*)d_in[7];
    const float* Wo    = (const float*)d_in[8];
    const float* bo    = (const float*)d_in[9];
    const float* W1    = (const float*)d_in[10];
    const float* b1    = (const float*)d_in[11];
    const float* W2    = (const float*)d_in[12];
    const float* b2    = (const float*)d_in[13];
    const float* g1    = (const float*)d_in[14];
    const float* beta1 = (const float*)d_in[15];
    const float* g2    = (const float*)d_in[16];
    const float* beta2 = (const float*)d_in[17];
    float* out = (float*)d_out;

    float *xn, *q, *k, *v, *ctx, *x2, *hbuf;
    cudaGetSymbolAddress((void**)&xn,   g_xn);
    cudaGetSymbolAddress((void**)&q,    g_q);
    cudaGetSymbolAddress((void**)&k,    g_k);
    cudaGetSymbolAddress((void**)&v,    g_v);
    cudaGetSymbolAddress((void**)&ctx,  g_ctx);
    cudaGetSymbolAddress((void**)&x2,   g_x2);
    cudaGetSymbolAddress((void**)&hbuf, g_h);

    static bool attr_set = false;
    if (!attr_set) {
        cudaFuncSetAttribute(attn_kernel, cudaFuncAttributeMaxDynamicSharedMemorySize,
                             ATTN_SMEM_FLOATS * (int)sizeof(float));
        attr_set = true;
    }

    const int M = MROWS, D = DMODEL, F = FFDIM;

    // LN1
    ln_kernel<<<M, 256>>>(x, g1, beta1, xn);

    // QKV projections
    dim3 gD(D / BN, M / BM);
    gemm_nt<<<gD, 256>>>(xn, Wq, bq, nullptr, q, M, D, D, 0);
    gemm_nt<<<gD, 256>>>(xn, Wk, bk, nullptr, k, M, D, D, 0);
    gemm_nt<<<gD, 256>>>(xn, Wv, bv, nullptr, v, M, D, D, 0);

    // causal attention
    dim3 gA(SEQ / AQ, BSZ * NHEADS);
    attn_kernel<<<gA, 512, ATTN_SMEM_FLOATS * sizeof(float)>>>(q, k, v, ctx);

    // output projection + residual
    gemm_nt<<<gD, 256>>>(ctx, Wo, bo, x, x2, M, D, D, 2);

    // LN2
    ln_kernel<<<M, 256>>>(x2, g2, beta2, xn);

    // FFN
    dim3 gF1(F / BN, M / BM);
    gemm_nt<<<gF1, 256>>>(xn, W1, b1, nullptr, hbuf, M, F, D, 1);
    gemm_nt<<<gD, 256>>>(hbuf, W2, b2, x2, out, M, D, F, 2);
}

// round 2
// speedup vs baseline: 1.5557x; 1.5557x over previous
#include <cuda_runtime.h>
#include <cuda_fp16.h>
#include <math.h>
#include <stdint.h>

// ---------------- problem constants ----------------
#define BSZ   2
#define SEQ   2048
#define DMODEL 1024
#define NHEADS 16
#define HDIM   64
#define FFDIM  4096
#define MROWS (BSZ*SEQ)          // 4096
#define LN_EPS 1e-5f

// ---------------- scratch (device globals; no allocs) ----------------
__device__ float g_xn [MROWS*DMODEL];
__device__ float g_q  [MROWS*DMODEL];
__device__ float g_k  [MROWS*DMODEL];
__device__ float g_v  [MROWS*DMODEL];
__device__ float g_ctx[MROWS*DMODEL];
__device__ float g_x2 [MROWS*DMODEL];
__device__ float g_h  [MROWS*FFDIM];
// fp16 split scratch: A' = [Ah|Ah|Al] (activations), B' = [Bh|Bl|Bh] (weights)
__device__ __half g_act_h[(size_t)MROWS * 3 * FFDIM];   // big enough for K'=12288
__device__ __half g_w_h  [(size_t)FFDIM * 3 * DMODEL];  // 4096*3072 >= 1024*12288

// ---------------- LayerNorm (one block per row of 1024) ----------------
__global__ __launch_bounds__(256) void ln_kernel(const float* __restrict__ x,
                                                 const float* __restrict__ g,
                                                 const float* __restrict__ b,
                                                 float* __restrict__ out) {
    int row = blockIdx.x;
    int t   = threadIdx.x;
    const float4 v = ((const float4*)(x + (size_t)row * DMODEL))[t];
    float s  = v.x + v.y + v.z + v.w;
    float ss = v.x*v.x + v.y*v.y + v.z*v.z + v.w*v.w;
    #pragma unroll
    for (int o = 16; o; o >>= 1) {
        s  += __shfl_xor_sync(0xffffffffu, s,  o);
        ss += __shfl_xor_sync(0xffffffffu, ss, o);
    }
    __shared__ float rs[8], rss[8];
    if ((t & 31) == 0) { rs[t >> 5] = s; rss[t >> 5] = ss; }
    __syncthreads();
    float S = 0.f, SS = 0.f;
    #pragma unroll
    for (int i = 0; i < 8; i++) { S += rs[i]; SS += rss[i]; }
    float mean = S * (1.f / DMODEL);
    float var  = SS * (1.f / DMODEL) - mean * mean;
    float rstd = rsqrtf(var + LN_EPS);
    const float4 gv = ((const float4*)g)[t];
    const float4 bv = ((const float4*)b)[t];
    float4 o4;
    o4.x = (v.x - mean) * rstd * gv.x + bv.x;
    o4.y = (v.y - mean) * rstd * gv.y + bv.y;
    o4.z = (v.z - mean) * rstd * gv.z + bv.z;
    o4.w = (v.w - mean) * rstd * gv.w + bv.w;
    ((float4*)(out + (size_t)row * DMODEL))[t] = o4;
}

// ---------------- fp32 -> fp16 hi/lo split, K' = 3K concatenated ----------------
// actmode=1: [hi | hi | lo]   actmode=0 (weights): [hi | lo | hi]
__global__ __launch_bounds__(256) void split3(const float* __restrict__ src,
                                              __half* __restrict__ dst,
                                              int kshift, int actmode) {
    size_t i = ((size_t)blockIdx.x * 256 + threadIdx.x) * 2;
    int K = 1 << kshift;
    size_t r = i >> kshift;
    int    c = (int)(i & (size_t)(K - 1));
    float2 f = *(const float2*)(src + i);
    __half2 hi = __floats2half2_rn(f.x, f.y);
    float2 fh = __half22float2(hi);
    __half2 lo = __floats2half2_rn(f.x - fh.x, f.y - fh.y);
    size_t base = r * (size_t)(3 * K);
    *(__half2*)(dst + base + c) = hi;
    if (actmode) {
        *(__half2*)(dst + base + K + c)     = hi;
        *(__half2*)(dst + base + 2 * K + c) = lo;
    } else {
        *(__half2*)(dst + base + K + c)     = lo;
        *(__half2*)(dst + base + 2 * K + c) = hi;
    }
}

// ---------------- tensor-core fp16 GEMM: C[M,N] = A'[M,Kt] @ B'[N,Kt]^T ----------------
// epi: 0 = bias, 1 = bias+GELU(exact), 2 = bias+residual
#define CP16(sa, ga) asm volatile("cp.async.cg.shared.global [%0], [%1], 16;\n" :: "r"(sa), "l"(ga))

__global__ __launch_bounds__(256) void hgemm(const __half* __restrict__ A,
                                             const __half* __restrict__ B,
                                             const float* __restrict__ bias,
                                             const float* __restrict__ R,
                                             float* __restrict__ C,
                                             int M, int N, int Kt, int epi) {
    __shared__ __align__(16) __half As[2][128][40];
    __shared__ __align__(16) __half Bs[2][128][40];

    const int tid  = threadIdx.x;
    const int wid  = tid >> 5;
    const int lane = tid & 31;
    const int bm   = blockIdx.y * 128;
    const int bn   = blockIdx.x * 128;
    const int wm0  = (wid >> 2) * 64;
    const int wn0  = (wid & 3) * 32;

    float acc[4][4][4];
    #pragma unroll
    for (int i = 0; i < 4; i++)
        #pragma unroll
        for (int j = 0; j < 4; j++)
            #pragma unroll
            for (int t = 0; t < 4; t++) acc[i][j][t] = 0.f;

    const int nk = Kt >> 5;   // BK = 32

    // ---- prefetch stage 0 ----
    {
        #pragma unroll
        for (int it = 0; it < 2; it++) {
            int c = tid + it * 256;
            int row = c >> 2, seg = (c & 3) * 8;
            const __half* ga = A + (size_t)(bm + row) * Kt + seg;
            uint32_t sa = (uint32_t)__cvta_generic_to_shared(&As[0][row][seg]);
            CP16(sa, ga);
            const __half* gb = B + (size_t)(bn + row) * Kt + seg;
            uint32_t sb = (uint32_t)__cvta_generic_to_shared(&Bs[0][row][seg]);
            CP16(sb, gb);
        }
        asm volatile("cp.async.commit_group;\n" ::);
    }

    for (int kt = 0; kt < nk; kt++) {
        const int buf = kt & 1;
        if (kt + 1 < nk) {
            int k0 = (kt + 1) << 5;
            #pragma unroll
            for (int it = 0; it < 2; it++) {
                int c = tid + it * 256;
                int row = c >> 2, seg = (c & 3) * 8;
                const __half* ga = A + (size_t)(bm + row) * Kt + k0 + seg;
                uint32_t sa = (uint32_t)__cvta_generic_to_shared(&As[buf ^ 1][row][seg]);
                CP16(sa, ga);
                const __half* gb = B + (size_t)(bn + row) * Kt + k0 + seg;
                uint32_t sb = (uint32_t)__cvta_generic_to_shared(&Bs[buf ^ 1][row][seg]);
                CP16(sb, gb);
            }
            asm volatile("cp.async.commit_group;\n" ::);
            asm volatile("cp.async.wait_group 1;\n" ::);
        } else {
            asm volatile("cp.async.wait_group 0;\n" ::);
        }
        __syncthreads();

        #pragma unroll
        for (int ks = 0; ks < 2; ks++) {
            const int fcol = ks * 16 + ((lane >> 4) << 3);
            // B fragments for the two 16-wide n-tile pairs
            uint32_t b[2][4];
            #pragma unroll
            for (int nt2 = 0; nt2 < 2; nt2++) {
                uint32_t addr = (uint32_t)__cvta_generic_to_shared(
                    &Bs[buf][wn0 + nt2 * 16 + (lane & 15)][fcol]);
                asm volatile("ldmatrix.sync.aligned.m8n8.x4.shared.b16 {%0,%1,%2,%3}, [%4];"
                             : "=r"(b[nt2][0]), "=r"(b[nt2][1]), "=r"(b[nt2][2]), "=r"(b[nt2][3])
                             : "r"(addr));
            }
            #pragma unroll
            for (int mt = 0; mt < 4; mt++) {
                uint32_t a0, a1, a2, a3;
                uint32_t addr = (uint32_t)__cvta_generic_to_shared(
                    &As[buf][wm0 + mt * 16 + (lane & 15)][fcol]);
                asm volatile("ldmatrix.sync.aligned.m8n8.x4.shared.b16 {%0,%1,%2,%3}, [%4];"
                             : "=r"(a0), "=r"(a1), "=r"(a2), "=r"(a3)
                             : "r"(addr));
                #pragma unroll
                for (int nt = 0; nt < 4; nt++) {
                    const int nt2 = nt >> 1, sub = nt & 1;
                    asm volatile(
                        "mma.sync.aligned.m16n8k16.row.col.f32.f16.f16.f32 "
                        "{%0,%1,%2,%3}, {%4,%5,%6,%7}, {%8,%9}, {%0,%1,%2,%3};"
                        : "+f"(acc[mt][nt][0]), "+f"(acc[mt][nt][1]),
                          "+f"(acc[mt][nt][2]), "+f"(acc[mt][nt][3])
                        : "r"(a0), "r"(a1), "r"(a2), "r"(a3),
                          "r"(b[nt2][sub]), "r"(b[nt2][sub + 2]));
                }
            }
        }
        __syncthreads();
    }

    // ---- epilogue ----
    const int g  = lane >> 2;
    const int tg = lane & 3;
    #pragma unroll
    for (int mt = 0; mt < 4; mt++) {
        #pragma unroll
        for (int nt = 0; nt < 4; nt++) {
            const int col = bn + wn0 + nt * 8 + tg * 2;
            const float bx = bias[col], by = bias[col + 1];
            #pragma unroll
            for (int hh = 0; hh < 2; hh++) {
                const int row = bm + wm0 + mt * 16 + g + hh * 8;
                float v0 = acc[mt][nt][hh * 2 + 0] + bx;
                float v1 = acc[mt][nt][hh * 2 + 1] + by;
                if (epi == 1) {
                    v0 = 0.5f * v0 * (1.0f + erff(v0 * 0.7071067811865475f));
                    v1 = 0.5f * v1 * (1.0f + erff(v1 * 0.7071067811865475f));
                } else if (epi == 2) {
                    const float2 rv = *(const float2*)&R[(size_t)row * N + col];
                    v0 += rv.x; v1 += rv.y;
                }
                float2 o; o.x = v0; o.y = v1;
                *(float2*)&C[(size_t)row * N + col] = o;
            }
        }
    }
}

// ---------------- causal flash attention (fp32) ----------------
#define AQ 64
#define AC 64
#define SK_STRIDE 65
#define SMEM_SK  0
#define SMEM_SV  (AC * SK_STRIDE)
#define SMEM_SQ  (SMEM_SV + AC * HDIM)
#define SMEM_SP  (SMEM_SQ + AQ * HDIM)
#define ATTN_SMEM_FLOATS (SMEM_SP + AQ * AC)

__global__ __launch_bounds__(512) void attn_kernel(const float* __restrict__ Q,
                                                   const float* __restrict__ K,
                                                   const float* __restrict__ V,
                                                   float* __restrict__ O) {
    extern __shared__ float sm[];
    float* sK = sm + SMEM_SK;
    float* sV = sm + SMEM_SV;
    float* sQ = sm + SMEM_SQ;
    float* sP = sm + SMEM_SP;

    const int bh = blockIdx.y;
    const int b  = bh >> 4;
    const int h  = bh & 15;
    const int q0 = blockIdx.x * AQ;

    const size_t base = ((size_t)b * SEQ) * DMODEL + (size_t)h * HDIM;
    const float* Qb = Q + base + (size_t)q0 * DMODEL;
    const float* Kb = K + base;
    const float* Vb = V + base;
    float*       Ob = O + base + (size_t)q0 * DMODEL;

    const int tid  = threadIdx.x;
    const int w    = tid >> 5;
    const int lane = tid & 31;

    for (int idx = tid; idx < AQ * HDIM; idx += 512) {
        int r = idx >> 6, d = idx & 63;
        sQ[r * HDIM + d] = Qb[(size_t)r * DMODEL + d];
    }

    int   rl[4];
    float m[4], l[4], a0[4], a1[4];
    #pragma unroll
    for (int i = 0; i < 4; i++) {
        rl[i] = w + i * 16;
        m[i] = -1e30f; l[i] = 0.f; a0[i] = 0.f; a1[i] = 0.f;
    }
    __syncthreads();

    const int kend = q0 + AQ;
    for (int c0 = 0; c0 < kend; c0 += AC) {
        for (int idx = tid; idx < AC * HDIM; idx += 512) {
            int j = idx >> 6, d = idx & 63;
            float kv = Kb[(size_t)(c0 + j) * DMODEL + d];
            sK[d * SK_STRIDE + j] = kv;
            sV[j * HDIM + d]      = Vb[(size_t)(c0 + j) * DMODEL + d];
        }
        __syncthreads();

        float s0[4] = {0,0,0,0}, s1[4] = {0,0,0,0};
        #pragma unroll 8
        for (int d = 0; d < HDIM; d++) {
            float k0v = sK[d * SK_STRIDE + lane];
            float k1v = sK[d * SK_STRIDE + lane + 32];
            #pragma unroll
            for (int i = 0; i < 4; i++) {
                float qd = sQ[rl[i] * HDIM + d];
                s0[i] += qd * k0v;
                s1[i] += qd * k1v;
            }
        }

        #pragma unroll
        for (int i = 0; i < 4; i++) {
            int row = q0 + rl[i];
            float x0 = (c0 + lane      <= row) ? s0[i] * 0.125f : -1e30f;
            float x1 = (c0 + lane + 32 <= row) ? s1[i] * 0.125f : -1e30f;
            float mx = fmaxf(x0, x1);
            #pragma unroll
            for (int o = 16; o; o >>= 1) mx = fmaxf(mx, __shfl_xor_sync(0xffffffffu, mx, o));
            float mn   = fmaxf(m[i], mx);
            float corr = __expf(m[i] - mn);
            float p0   = __expf(x0 - mn);
            float p1   = __expf(x1 - mn);
            float ps   = p0 + p1;
            #pragma unroll
            for (int o = 16; o; o >>= 1) ps += __shfl_xor_sync(0xffffffffu, ps, o);
            l[i]  = l[i] * corr + ps;
            a0[i] *= corr;
            a1[i] *= corr;
            m[i]  = mn;
            sP[rl[i] * AC + lane]      = p0;
            sP[rl[i] * AC + lane + 32] = p1;
        }
        __syncwarp();

        #pragma unroll 4
        for (int j = 0; j < AC; j++) {
            float v0 = sV[j * HDIM + lane];
            float v1 = sV[j * HDIM + lane + 32];
            #pragma unroll
            for (int i = 0; i < 4; i++) {
                float p = sP[rl[i] * AC + j];
                a0[i] += p * v0;
                a1[i] += p * v1;
            }
        }
        __syncthreads();
    }

    #pragma unroll
    for (int i = 0; i < 4; i++) {
        float inv = 1.f / l[i];
        Ob[(size_t)rl[i] * DMODEL + lane]      = a0[i] * inv;
        Ob[(size_t)rl[i] * DMODEL + lane + 32] = a1[i] * inv;
    }
}

// ---------------- launcher ----------------
extern "C" void kernel_launch(void* const* d_in, const int* in_sizes, int n_in,
                              void* d_out, int out_size) {
    const float* x     = (const float*)d_in[0];
    const float* Wq    = (const float*)d_in[2];
    const float* bq    = (const float*)d_in[3];
    const float* Wk    = (const float*)d_in[4];
    const float* bk    = (const float*)d_in[5];
    const float* Wv    = (const float*)d_in[6];
    const float* bv    = (const float*)d_in[7];
    const float* Wo    = (const float*)d_in[8];
    const float* bo    = (const float*)d_in[9];
    const float* W1    = (const float*)d_in[10];
    const float* b1    = (const float*)d_in[11];
    const float* W2    = (const float*)d_in[12];
    const float* b2    = (const float*)d_in[13];
    const float* g1    = (const float*)d_in[14];
    const float* beta1 = (const float*)d_in[15];
    const float* g2    = (const float*)d_in[16];
    const float* beta2 = (const float*)d_in[17];
    float* out = (float*)d_out;

    float *xn, *q, *k, *v, *ctx, *x2, *hbuf;
    __half *actH, *wH;
    cudaGetSymbolAddress((void**)&xn,   g_xn);
    cudaGetSymbolAddress((void**)&q,    g_q);
    cudaGetSymbolAddress((void**)&k,    g_k);
    cudaGetSymbolAddress((void**)&v,    g_v);
    cudaGetSymbolAddress((void**)&ctx,  g_ctx);
    cudaGetSymbolAddress((void**)&x2,   g_x2);
    cudaGetSymbolAddress((void**)&hbuf, g_h);
    cudaGetSymbolAddress((void**)&actH, g_act_h);
    cudaGetSymbolAddress((void**)&wH,   g_w_h);

    static bool attr_set = false;
    if (!attr_set) {
        cudaFuncSetAttribute(attn_kernel, cudaFuncAttributeMaxDynamicSharedMemorySize,
                             ATTN_SMEM_FLOATS * (int)sizeof(float));
        attr_set = true;
    }

    const int M = MROWS, D = DMODEL, F = FFDIM;
    const int KSH_D = 10;  // log2(1024)
    const int KSH_F = 12;  // log2(4096)

    // LN1
    ln_kernel<<<M, 256>>>(x, g1, beta1, xn);

    // QKV projections (fp16x3 tensor-core GEMMs, K'=3072)
    split3<<<(M * D / 2) / 256, 256>>>(xn, actH, KSH_D, 1);
    dim3 gD(D / 128, M / 128);
    split3<<<(D * D / 2) / 256, 256>>>(Wq, wH, KSH_D, 0);
    hgemm<<<gD, 256>>>(actH, wH, bq, nullptr, q, M, D, 3 * D, 0);
    split3<<<(D * D / 2) / 256, 256>>>(Wk, wH, KSH_D, 0);
    hgemm<<<gD, 256>>>(actH, wH, bk, nullptr, k, M, D, 3 * D, 0);
    split3<<<(D * D / 2) / 256, 256>>>(Wv, wH, KSH_D, 0);
    hgemm<<<gD, 256>>>(actH, wH, bv, nullptr, v, M, D, 3 * D, 0);

    // causal attention
    dim3 gA(SEQ / AQ, BSZ * NHEADS);
    attn_kernel<<<gA, 512, ATTN_SMEM_FLOATS * sizeof(float)>>>(q, k, v, ctx);

    // output projection + residual
    split3<<<(M * D / 2) / 256, 256>>>(ctx, actH, KSH_D, 1);
    split3<<<(D * D / 2) / 256, 256>>>(Wo, wH, KSH_D, 0);
    hgemm<<<gD, 256>>>(actH, wH, bo, x, x2, M, D, 3 * D, 2);

    // LN2
    ln_kernel<<<M, 256>>>(x2, g2, beta2, xn);

    // FFN1: [M,4096] = GELU([M,1024] @ W1^T + b1)
    split3<<<(M * D / 2) / 256, 256>>>(xn, actH, KSH_D, 1);
    split3<<<(F * D / 2) / 256, 256>>>(W1, wH, KSH_D, 0);
    dim3 gF1(F / 128, M / 128);
    hgemm<<<gF1, 256>>>(actH, wH, b1, nullptr, hbuf, M, F, 3 * D, 1);

    // FFN2: out = x2 + h @ W2^T + b2   (K'=12288)
    split3<<<((size_t)M * F / 2) / 256, 256>>>(hbuf, actH, KSH_F, 1);
    split3<<<((size_t)D * F / 2) / 256, 256>>>(W2, wH, KSH_F, 0);
    hgemm<<<gD, 256>>>(actH, wH, b2, x2, out, M, D, 3 * F, 2);
}

// round 3
// speedup vs baseline: 1.8114x; 1.1643x over previous
#include <cuda_runtime.h>
#include <cuda_fp16.h>
#include <math.h>
#include <stdint.h>

// ---------------- problem constants ----------------
#define BSZ    2
#define SEQ    2048
#define DMODEL 1024
#define NHEADS 16
#define HDIM   64
#define FFDIM  4096
#define MROWS (BSZ*SEQ)          // 4096
#define QKVW  (3*DMODEL)         // 3072
#define LN_EPS 1e-5f

// ---------------- scratch (device globals; no allocs) ----------------
__device__ float g_xn  [MROWS*DMODEL];
__device__ float g_qkv [(size_t)MROWS*QKVW];
__device__ float g_ctx [MROWS*DMODEL];
__device__ float g_x2  [MROWS*DMODEL];
__device__ float g_h   [(size_t)MROWS*FFDIM];
__device__ float g_bqkv[QKVW];
// hi/lo fp16 split buffers
__device__ __half g_ah[(size_t)MROWS*FFDIM];
__device__ __half g_al[(size_t)MROWS*FFDIM];
__device__ __half g_wh[(size_t)FFDIM*DMODEL];
__device__ __half g_wl[(size_t)FFDIM*DMODEL];

// ---------------- LayerNorm ----------------
__global__ __launch_bounds__(256) void ln_kernel(const float* __restrict__ x,
                                                 const float* __restrict__ g,
                                                 const float* __restrict__ b,
                                                 float* __restrict__ out) {
    int row = blockIdx.x;
    int t   = threadIdx.x;
    const float4 v = ((const float4*)(x + (size_t)row * DMODEL))[t];
    float s  = v.x + v.y + v.z + v.w;
    float ss = v.x*v.x + v.y*v.y + v.z*v.z + v.w*v.w;
    #pragma unroll
    for (int o = 16; o; o >>= 1) {
        s  += __shfl_xor_sync(0xffffffffu, s,  o);
        ss += __shfl_xor_sync(0xffffffffu, ss, o);
    }
    __shared__ float rs[8], rss[8];
    if ((t & 31) == 0) { rs[t >> 5] = s; rss[t >> 5] = ss; }
    __syncthreads();
    float S = 0.f, SS = 0.f;
    #pragma unroll
    for (int i = 0; i < 8; i++) { S += rs[i]; SS += rss[i]; }
    float mean = S * (1.f / DMODEL);
    float var  = SS * (1.f / DMODEL) - mean * mean;
    float rstd = rsqrtf(var + LN_EPS);
    const float4 gv = ((const float4*)g)[t];
    const float4 bv = ((const float4*)b)[t];
    float4 o4;
    o4.x = (v.x - mean) * rstd * gv.x + bv.x;
    o4.y = (v.y - mean) * rstd * gv.y + bv.y;
    o4.z = (v.z - mean) * rstd * gv.z + bv.z;
    o4.w = (v.w - mean) * rstd * gv.w + bv.w;
    ((float4*)(out + (size_t)row * DMODEL))[t] = o4;
}

// ---------------- fp32 -> (hi, lo) fp16 split, layout-preserving ----------------
__global__ __launch_bounds__(256) void split2(const float* __restrict__ src,
                                              __half* __restrict__ dh,
                                              __half* __restrict__ dl) {
    size_t i = ((size_t)blockIdx.x * 256 + threadIdx.x) * 2;
    float2 f = *(const float2*)(src + i);
    __half2 hi = __floats2half2_rn(f.x, f.y);
    float2 fh = __half22float2(hi);
    __half2 lo = __floats2half2_rn(f.x - fh.x, f.y - fh.y);
    *(__half2*)(dh + i) = hi;
    *(__half2*)(dl + i) = lo;
}

__global__ void pack_bias(const float* __restrict__ a, const float* __restrict__ b,
                          const float* __restrict__ c, float* __restrict__ out) {
    int i = blockIdx.x * 256 + threadIdx.x;
    float v = (i < 1024) ? a[i] : (i < 2048) ? b[i - 1024] : c[i - 2048];
    out[i] = v;
}

// ---------------- compensated fp16 tensor-core GEMM ----------------
// C[M,N] = (Ah+Al)[M,K] @ (Bh+Bl)[N,K]^T  (drops Al*Bl)
// epi: 0 = bias, 1 = bias+GELU(exact), 2 = bias+residual
#define CP16(sa, ga) asm volatile("cp.async.cg.shared.global [%0], [%1], 16;\n" :: "r"(sa), "l"(ga))
#define LDMX4(r0,r1,r2,r3,addr) asm volatile( \
    "ldmatrix.sync.aligned.m8n8.x4.shared.b16 {%0,%1,%2,%3}, [%4];" \
    : "=r"(r0), "=r"(r1), "=r"(r2), "=r"(r3) : "r"(addr))
#define MMA16816(d, a0,a1,a2,a3, b0,b1) asm volatile( \
    "mma.sync.aligned.m16n8k16.row.col.f32.f16.f16.f32 " \
    "{%0,%1,%2,%3}, {%4,%5,%6,%7}, {%8,%9}, {%0,%1,%2,%3};" \
    : "+f"(d[0]), "+f"(d[1]), "+f"(d[2]), "+f"(d[3]) \
    : "r"(a0), "r"(a1), "r"(a2), "r"(a3), "r"(b0), "r"(b1))

#define TILE_H  (128 * 40)          // halves per 128x32 tile (stride 40)
#define STAGE_H (4 * TILE_H)        // Ah,Al,Bh,Bl
#define GSMEM_BYTES (2 * STAGE_H * 2)

__global__ __launch_bounds__(256, 2) void hgemm3(const __half* __restrict__ Ah,
                                                 const __half* __restrict__ Al,
                                                 const __half* __restrict__ Bh,
                                                 const __half* __restrict__ Bl,
                                                 const float* __restrict__ bias,
                                                 const float* __restrict__ R,
                                                 float* __restrict__ C,
                                                 int M, int N, int K, int epi) {
    extern __shared__ __half sm16[];

    const int tid  = threadIdx.x;
    const int wid  = tid >> 5;
    const int lane = tid & 31;
    const int bm   = blockIdx.y * 128;
    const int bn   = blockIdx.x * 128;
    const int wm0  = (wid >> 2) * 64;
    const int wn0  = (wid & 3) * 32;

    float acc[4][4][4];
    #pragma unroll
    for (int i = 0; i < 4; i++)
        #pragma unroll
        for (int j = 0; j < 4; j++)
            #pragma unroll
            for (int t = 0; t < 4; t++) acc[i][j][t] = 0.f;

    const int nk = K >> 5;

    // per-thread load coords (2 chunks per tile)
    const int r0 = tid >> 2,       s0 = (tid & 3) * 8;
    const int r1 = (tid + 256) >> 2, s1 = ((tid + 256) & 3) * 8;

    // smem byte base addresses for this thread's cp.async destinations
    const uint32_t smBase = (uint32_t)__cvta_generic_to_shared(sm16);
    #define SADDR(stage, tile, row, col) (smBase + (((stage)*STAGE_H + (tile)*TILE_H + (row)*40 + (col)) << 1))

    // global row bases
    const __half* gAh = Ah + (size_t)bm * K;
    const __half* gAl = Al + (size_t)bm * K;
    const __half* gBh = Bh + (size_t)bn * K;
    const __half* gBl = Bl + (size_t)bn * K;

    #define LOAD_STAGE(stg, k0)  do {                                          \
        CP16(SADDR(stg,0,r0,s0), gAh + (size_t)r0 * K + (k0) + s0);            \
        CP16(SADDR(stg,0,r1,s1), gAh + (size_t)r1 * K + (k0) + s1);            \
        CP16(SADDR(stg,1,r0,s0), gAl + (size_t)r0 * K + (k0) + s0);            \
        CP16(SADDR(stg,1,r1,s1), gAl + (size_t)r1 * K + (k0) + s1);            \
        CP16(SADDR(stg,2,r0,s0), gBh + (size_t)r0 * K + (k0) + s0);            \
        CP16(SADDR(stg,2,r1,s1), gBh + (size_t)r1 * K + (k0) + s1);            \
        CP16(SADDR(stg,3,r0,s0), gBl + (size_t)r0 * K + (k0) + s0);            \
        CP16(SADDR(stg,3,r1,s1), gBl + (size_t)r1 * K + (k0) + s1);            \
        asm volatile("cp.async.commit_group;\n" ::);                           \
    } while (0)

    LOAD_STAGE(0, 0);

    // fragment smem addresses (vary only by stage & ks & mt/nt2 constants)
    const int aRow = (lane & 15);
    const int fBase = ((lane >> 4) << 3);

    for (int kt = 0; kt < nk; kt++) {
        const int buf = kt & 1;
        if (kt + 1 < nk) {
            LOAD_STAGE(buf ^ 1, (kt + 1) << 5);
            asm volatile("cp.async.wait_group 1;\n" ::);
        } else {
            asm volatile("cp.async.wait_group 0;\n" ::);
        }
        __syncthreads();

        #pragma unroll
        for (int ks = 0; ks < 2; ks++) {
            const int fcol = ks * 16 + fBase;
            uint32_t bh[2][4], bl[2][4];
            #pragma unroll
            for (int nt2 = 0; nt2 < 2; nt2++) {
                LDMX4(bh[nt2][0], bh[nt2][1], bh[nt2][2], bh[nt2][3],
                      SADDR(buf, 2, wn0 + nt2 * 16 + aRow, fcol));
                LDMX4(bl[nt2][0], bl[nt2][1], bl[nt2][2], bl[nt2][3],
                      SADDR(buf, 3, wn0 + nt2 * 16 + aRow, fcol));
            }
            #pragma unroll
            for (int mt = 0; mt < 4; mt++) {
                uint32_t a0, a1, a2, a3;
                LDMX4(a0, a1, a2, a3, SADDR(buf, 0, wm0 + mt * 16 + aRow, fcol));
                #pragma unroll
                for (int nt = 0; nt < 4; nt++)
                    MMA16816(acc[mt][nt], a0, a1, a2, a3,
                             bh[nt >> 1][nt & 1], bh[nt >> 1][(nt & 1) + 2]);
                #pragma unroll
                for (int nt = 0; nt < 4; nt++)
                    MMA16816(acc[mt][nt], a0, a1, a2, a3,
                             bl[nt >> 1][nt & 1], bl[nt >> 1][(nt & 1) + 2]);
                uint32_t c0, c1, c2, c3;
                LDMX4(c0, c1, c2, c3, SADDR(buf, 1, wm0 + mt * 16 + aRow, fcol));
                #pragma unroll
                for (int nt = 0; nt < 4; nt++)
                    MMA16816(acc[mt][nt], c0, c1, c2, c3,
                             bh[nt >> 1][nt & 1], bh[nt >> 1][(nt & 1) + 2]);
            }
        }
        __syncthreads();
    }

    // ---- epilogue ----
    const int g  = lane >> 2;
    const int tg = lane & 3;
    #pragma unroll
    for (int mt = 0; mt < 4; mt++) {
        #pragma unroll
        for (int nt = 0; nt < 4; nt++) {
            const int col = bn + wn0 + nt * 8 + tg * 2;
            const float bx = bias[col], by = bias[col + 1];
            #pragma unroll
            for (int hh = 0; hh < 2; hh++) {
                const int row = bm + wm0 + mt * 16 + g + hh * 8;
                float v0 = acc[mt][nt][hh * 2 + 0] + bx;
                float v1 = acc[mt][nt][hh * 2 + 1] + by;
                if (epi == 1) {
                    v0 = 0.5f * v0 * (1.0f + erff(v0 * 0.7071067811865475f));
                    v1 = 0.5f * v1 * (1.0f + erff(v1 * 0.7071067811865475f));
                } else if (epi == 2) {
                    const float2 rv = *(const float2*)&R[(size_t)row * N + col];
                    v0 += rv.x; v1 += rv.y;
                }
                float2 o; o.x = v0; o.y = v1;
                *(float2*)&C[(size_t)row * N + col] = o;
            }
        }
    }
}

// ---------------- causal flash attention (fp32, fused-QKV input) ----------------
#define AQ 64
#define AC 64
#define SK_STRIDE 65
#define SMEM_SK  0
#define SMEM_SV  (AC * SK_STRIDE)
#define SMEM_SQ  (SMEM_SV + AC * HDIM)
#define SMEM_SP  (SMEM_SQ + AQ * HDIM)
#define ATTN_SMEM_FLOATS (SMEM_SP + AQ * AC)

__global__ __launch_bounds__(512) void attn_kernel(const float* __restrict__ QKV,
                                                   float* __restrict__ O) {
    extern __shared__ float sm[];
    float* sK = sm + SMEM_SK;
    float* sV = sm + SMEM_SV;
    float* sQ = sm + SMEM_SQ;
    float* sP = sm + SMEM_SP;

    const int bh = blockIdx.y;
    const int b  = bh >> 4;
    const int h  = bh & 15;
    const int q0 = blockIdx.x * AQ;

    const size_t base = ((size_t)b * SEQ) * QKVW + (size_t)h * HDIM;
    const float* Qb = QKV + base + (size_t)q0 * QKVW;
    const float* Kb = QKV + base + DMODEL;
    const float* Vb = QKV + base + 2 * DMODEL;
    float*       Ob = O + ((size_t)b * SEQ + q0) * DMODEL + (size_t)h * HDIM;

    const int tid  = threadIdx.x;
    const int w    = tid >> 5;
    const int lane = tid & 31;

    for (int idx = tid; idx < AQ * HDIM; idx += 512) {
        int r = idx >> 6, d = idx & 63;
        sQ[r * HDIM + d] = Qb[(size_t)r * QKVW + d];
    }

    int   rl[4];
    float m[4], l[4], a0[4], a1[4];
    #pragma unroll
    for (int i = 0; i < 4; i++) {
        rl[i] = w + i * 16;
        m[i] = -1e30f; l[i] = 0.f; a0[i] = 0.f; a1[i] = 0.f;
    }
    __syncthreads();

    const int kend = q0 + AQ;
    for (int c0 = 0; c0 < kend; c0 += AC) {
        for (int idx = tid; idx < AC * HDIM; idx += 512) {
            int j = idx >> 6, d = idx & 63;
            sK[d * SK_STRIDE + j] = Kb[(size_t)(c0 + j) * QKVW + d];
            sV[j * HDIM + d]      = Vb[(size_t)(c0 + j) * QKVW + d];
        }
        __syncthreads();

        float s0[4] = {0,0,0,0}, s1[4] = {0,0,0,0};
        #pragma unroll 8
        for (int d = 0; d < HDIM; d++) {
            float k0v = sK[d * SK_STRIDE + lane];
            float k1v = sK[d * SK_STRIDE + lane + 32];
            #pragma unroll
            for (int i = 0; i < 4; i++) {
                float qd = sQ[rl[i] * HDIM + d];
                s0[i] += qd * k0v;
                s1[i] += qd * k1v;
            }
        }

        #pragma unroll
        for (int i = 0; i < 4; i++) {
            int row = q0 + rl[i];
            float x0 = (c0 + lane      <= row) ? s0[i] * 0.125f : -1e30f;
            float x1 = (c0 + lane + 32 <= row) ? s1[i] * 0.125f : -1e30f;
            float mx = fmaxf(x0, x1);
            #pragma unroll
            for (int o = 16; o; o >>= 1) mx = fmaxf(mx, __shfl_xor_sync(0xffffffffu, mx, o));
            float mn   = fmaxf(m[i], mx);
            float corr = __expf(m[i] - mn);
            float p0   = __expf(x0 - mn);
            float p1   = __expf(x1 - mn);
            float ps   = p0 + p1;
            #pragma unroll
            for (int o = 16; o; o >>= 1) ps += __shfl_xor_sync(0xffffffffu, ps, o);
            l[i]  = l[i] * corr + ps;
            a0[i] *= corr;
            a1[i] *= corr;
            m[i]  = mn;
            sP[rl[i] * AC + lane]      = p0;
            sP[rl[i] * AC + lane + 32] = p1;
        }
        __syncwarp();

        #pragma unroll 4
        for (int j = 0; j < AC; j++) {
            float v0 = sV[j * HDIM + lane];
            float v1 = sV[j * HDIM + lane + 32];
            #pragma unroll
            for (int i = 0; i < 4; i++) {
                float p = sP[rl[i] * AC + j];
                a0[i] += p * v0;
                a1[i] += p * v1;
            }
        }
        __syncthreads();
    }

    #pragma unroll
    for (int i = 0; i < 4; i++) {
        float inv = 1.f / l[i];
        Ob[(size_t)rl[i] * DMODEL + lane]      = a0[i] * inv;
        Ob[(size_t)rl[i] * DMODEL + lane + 32] = a1[i] * inv;
    }
}

// ---------------- launcher ----------------
extern "C" void kernel_launch(void* const* d_in, const int* in_sizes, int n_in,
                              void* d_out, int out_size) {
    const float* x     = (const float*)d_in[0];
    const float* Wq    = (const float*)d_in[2];
    const float* bq    = (const float*)d_in[3];
    const float* Wk    = (const float*)d_in[4];
    const float* bk    = (const float*)d_in[5];
    const float* Wv    = (const float*)d_in[6];
    const float* bv    = (const float*)d_in[7];
    const float* Wo    = (const float*)d_in[8];
    const float* bo    = (const float*)d_in[9];
    const float* W1    = (const float*)d_in[10];
    const float* b1    = (const float*)d_in[11];
    const float* W2    = (const float*)d_in[12];
    const float* b2    = (const float*)d_in[13];
    const float* g1    = (const float*)d_in[14];
    const float* beta1 = (const float*)d_in[15];
    const float* g2    = (const float*)d_in[16];
    const float* beta2 = (const float*)d_in[17];
    float* out = (float*)d_out;

    float *xn, *qkv, *ctx, *x2, *hbuf, *bqkv;
    __half *ah, *al, *wh, *wl;
    cudaGetSymbolAddress((void**)&xn,   g_xn);
    cudaGetSymbolAddress((void**)&qkv,  g_qkv);
    cudaGetSymbolAddress((void**)&ctx,  g_ctx);
    cudaGetSymbolAddress((void**)&x2,   g_x2);
    cudaGetSymbolAddress((void**)&hbuf, g_h);
    cudaGetSymbolAddress((void**)&bqkv, g_bqkv);
    cudaGetSymbolAddress((void**)&ah,   g_ah);
    cudaGetSymbolAddress((void**)&al,   g_al);
    cudaGetSymbolAddress((void**)&wh,   g_wh);
    cudaGetSymbolAddress((void**)&wl,   g_wl);

    static bool attr_set = false;
    if (!attr_set) {
        cudaFuncSetAttribute(attn_kernel, cudaFuncAttributeMaxDynamicSharedMemorySize,
                             ATTN_SMEM_FLOATS * (int)sizeof(float));
        cudaFuncSetAttribute(hgemm3, cudaFuncAttributeMaxDynamicSharedMemorySize,
                             GSMEM_BYTES);
        attr_set = true;
    }

    const int M = MROWS, D = DMODEL, F = FFDIM;
    const size_t DD = (size_t)D * D;

    // LN1
    ln_kernel<<<M, 256>>>(x, g1, beta1, xn);

    // fused QKV GEMM (K=1024, N=3072)
    split2<<<(M * D / 2) / 256, 256>>>(xn, ah, al);
    split2<<<(int)(DD / 2) / 256, 256>>>(Wq, wh, wl);
    split2<<<(int)(DD / 2) / 256, 256>>>(Wk, wh + DD, wl + DD);
    split2<<<(int)(DD / 2) / 256, 256>>>(Wv, wh + 2 * DD, wl + 2 * DD);
    pack_bias<<<QKVW / 256, 256>>>(bq, bk, bv, bqkv);
    dim3 gQKV(QKVW / 128, M / 128);
    hgemm3<<<gQKV, 256, GSMEM_BYTES>>>(ah, al, wh, wl, bqkv, nullptr, qkv, M, QKVW, D, 0);

    // causal attention
    dim3 gA(SEQ / AQ, BSZ * NHEADS);
    attn_kernel<<<gA, 512, ATTN_SMEM_FLOATS * sizeof(float)>>>(qkv, ctx);

    // output projection + residual
    split2<<<(M * D / 2) / 256, 256>>>(ctx, ah, al);
    split2<<<(int)(DD / 2) / 256, 256>>>(Wo, wh, wl);
    dim3 gD(D / 128, M / 128);
    hgemm3<<<gD, 256, GSMEM_BYTES>>>(ah, al, wh, wl, bo, x, x2, M, D, D, 2);

    // LN2
    ln_kernel<<<M, 256>>>(x2, g2, beta2, xn);

    // FFN1
    split2<<<(M * D / 2) / 256, 256>>>(xn, ah, al);
    split2<<<(int)((size_t)F * D / 2) / 256, 256>>>(W1, wh, wl);
    dim3 gF1(F / 128, M / 128);
    hgemm3<<<gF1, 256, GSMEM_BYTES>>>(ah, al, wh, wl, b1, nullptr, hbuf, M, F, D, 1);

    // FFN2
    split2<<<(int)((size_t)M * F / 2) / 256, 256>>>(hbuf, ah, al);
    split2<<<(int)((size_t)D * F / 2) / 256, 256>>>(W2, wh, wl);
    hgemm3<<<gD, 256, GSMEM_BYTES>>>(ah, al, wh, wl, b2, x2, out, M, D, F, 2);
}

// round 4
// speedup vs baseline: 2.8710x; 1.5850x over previous
#include <cuda_runtime.h>
#include <cuda_fp16.h>
#include <math.h>
#include <stdint.h>

// ---------------- problem constants ----------------
#define BSZ    2
#define SEQ    2048
#define DMODEL 1024
#define NHEADS 16
#define HDIM   64
#define FFDIM  4096
#define MROWS (BSZ*SEQ)          // 4096
#define QKVW  (3*DMODEL)         // 3072
#define LN_EPS 1e-5f

// ---------------- scratch (device globals; no allocs) ----------------
__device__ float  g_x2  [MROWS*DMODEL];
__device__ float  g_bqkv[QKVW];
__device__ __half g_qkvh[(size_t)MROWS*QKVW];
__device__ __half g_ah[(size_t)MROWS*DMODEL];
__device__ __half g_al[(size_t)MROWS*DMODEL];
__device__ __half g_hh[(size_t)MROWS*FFDIM];
__device__ __half g_hl[(size_t)MROWS*FFDIM];
__device__ __half g_wh[(size_t)FFDIM*DMODEL];
__device__ __half g_wl[(size_t)FFDIM*DMODEL];

// ---------------- LayerNorm -> fp16 hi/lo split directly ----------------
__global__ __launch_bounds__(256) void ln_split(const float* __restrict__ x,
                                                const float* __restrict__ g,
                                                const float* __restrict__ b,
                                                __half* __restrict__ ah,
                                                __half* __restrict__ al) {
    int row = blockIdx.x;
    int t   = threadIdx.x;
    const float4 v = ((const float4*)(x + (size_t)row * DMODEL))[t];
    float s  = v.x + v.y + v.z + v.w;
    float ss = v.x*v.x + v.y*v.y + v.z*v.z + v.w*v.w;
    #pragma unroll
    for (int o = 16; o; o >>= 1) {
        s  += __shfl_xor_sync(0xffffffffu, s,  o);
        ss += __shfl_xor_sync(0xffffffffu, ss, o);
    }
    __shared__ float rs[8], rss[8];
    if ((t & 31) == 0) { rs[t >> 5] = s; rss[t >> 5] = ss; }
    __syncthreads();
    float S = 0.f, SS = 0.f;
    #pragma unroll
    for (int i = 0; i < 8; i++) { S += rs[i]; SS += rss[i]; }
    float mean = S * (1.f / DMODEL);
    float var  = SS * (1.f / DMODEL) - mean * mean;
    float rstd = rsqrtf(var + LN_EPS);
    const float4 gv = ((const float4*)g)[t];
    const float4 bv = ((const float4*)b)[t];
    float o0 = (v.x - mean) * rstd * gv.x + bv.x;
    float o1 = (v.y - mean) * rstd * gv.y + bv.y;
    float o2 = (v.z - mean) * rstd * gv.z + bv.z;
    float o3 = (v.w - mean) * rstd * gv.w + bv.w;
    __half2 h0 = __floats2half2_rn(o0, o1);
    __half2 h1 = __floats2half2_rn(o2, o3);
    float2 f0 = __half22float2(h0), f1 = __half22float2(h1);
    __half2 l0 = __floats2half2_rn(o0 - f0.x, o1 - f0.y);
    __half2 l1 = __floats2half2_rn(o2 - f1.x, o3 - f1.y);
    __half2* ph = (__half2*)(ah + (size_t)row * DMODEL);
    __half2* pl = (__half2*)(al + (size_t)row * DMODEL);
    ph[t*2] = h0; ph[t*2+1] = h1;
    pl[t*2] = l0; pl[t*2+1] = l1;
}

// ---------------- fp32 -> (hi, lo) fp16 split (weights) ----------------
__global__ __launch_bounds__(256) void split2(const float* __restrict__ src,
                                              __half* __restrict__ dh,
                                              __half* __restrict__ dl) {
    size_t i = ((size_t)blockIdx.x * 256 + threadIdx.x) * 2;
    float2 f = *(const float2*)(src + i);
    __half2 hi = __floats2half2_rn(f.x, f.y);
    float2 fh = __half22float2(hi);
    __half2 lo = __floats2half2_rn(f.x - fh.x, f.y - fh.y);
    *(__half2*)(dh + i) = hi;
    *(__half2*)(dl + i) = lo;
}

__global__ void pack_bias(const float* __restrict__ a, const float* __restrict__ b,
                          const float* __restrict__ c, float* __restrict__ out) {
    int i = blockIdx.x * 256 + threadIdx.x;
    float v = (i < 1024) ? a[i] : (i < 2048) ? b[i - 1024] : c[i - 2048];
    out[i] = v;
}

// ---------------- common PTX helpers ----------------
#define CP16(sa, ga) asm volatile("cp.async.cg.shared.global [%0], [%1], 16;\n" :: "r"(sa), "l"(ga))
#define LDMX4(r0,r1,r2,r3,addr) asm volatile( \
    "ldmatrix.sync.aligned.m8n8.x4.shared.b16 {%0,%1,%2,%3}, [%4];" \
    : "=r"(r0), "=r"(r1), "=r"(r2), "=r"(r3) : "r"(addr))
#define LDMX4T(r0,r1,r2,r3,addr) asm volatile( \
    "ldmatrix.sync.aligned.m8n8.x4.trans.shared.b16 {%0,%1,%2,%3}, [%4];" \
    : "=r"(r0), "=r"(r1), "=r"(r2), "=r"(r3) : "r"(addr))
#define MMA16816(d, a0,a1,a2,a3, b0,b1) asm volatile( \
    "mma.sync.aligned.m16n8k16.row.col.f32.f16.f16.f32 " \
    "{%0,%1,%2,%3}, {%4,%5,%6,%7}, {%8,%9}, {%0,%1,%2,%3};" \
    : "+f"(d[0]), "+f"(d[1]), "+f"(d[2]), "+f"(d[3]) \
    : "r"(a0), "r"(a1), "r"(a2), "r"(a3), "r"(b0), "r"(b1))
#define COMMIT() asm volatile("cp.async.commit_group;\n" ::)

// ---------------- compensated fp16 tensor-core GEMM ----------------
// C = (Ah+Al) @ (Bh+Bl)^T  (drops Al*Bl)
// epi: 2 = bias+residual -> float C
//      3 = bias          -> half Ch
//      4 = bias+GELU     -> half Ch + half Cl (hi/lo split)
#define TILE_H  (128 * 40)
#define STAGE_H (4 * TILE_H)
#define GSMEM_BYTES (2 * STAGE_H * 2)

__global__ __launch_bounds__(256, 2) void hgemm3(const __half* __restrict__ Ah,
                                                 const __half* __restrict__ Al,
                                                 const __half* __restrict__ Bh,
                                                 const __half* __restrict__ Bl,
                                                 const float* __restrict__ bias,
                                                 const float* __restrict__ R,
                                                 float* __restrict__ C,
                                                 __half* __restrict__ Ch,
                                                 __half* __restrict__ Cl,
                                                 int M, int N, int K, int epi) {
    extern __shared__ __half sm16[];

    const int tid  = threadIdx.x;
    const int wid  = tid >> 5;
    const int lane = tid & 31;
    const int bm   = blockIdx.y * 128;
    const int bn   = blockIdx.x * 128;
    const int wm0  = (wid >> 2) * 64;
    const int wn0  = (wid & 3) * 32;

    float acc[4][4][4];
    #pragma unroll
    for (int i = 0; i < 4; i++)
        #pragma unroll
        for (int j = 0; j < 4; j++)
            #pragma unroll
            for (int t = 0; t < 4; t++) acc[i][j][t] = 0.f;

    const int nk = K >> 5;
    const int r0 = tid >> 2,         s0 = (tid & 3) * 8;
    const int r1 = (tid + 256) >> 2, s1 = ((tid + 256) & 3) * 8;

    const uint32_t smBase = (uint32_t)__cvta_generic_to_shared(sm16);
    #define SADDR(stage, tile, row, col) (smBase + (((stage)*STAGE_H + (tile)*TILE_H + (row)*40 + (col)) << 1))

    const __half* gAh = Ah + (size_t)bm * K;
    const __half* gAl = Al + (size_t)bm * K;
    const __half* gBh = Bh + (size_t)bn * K;
    const __half* gBl = Bl + (size_t)bn * K;

    #define LOAD_STAGE(stg, k0)  do {                                          \
        CP16(SADDR(stg,0,r0,s0), gAh + (size_t)r0 * K + (k0) + s0);            \
        CP16(SADDR(stg,0,r1,s1), gAh + (size_t)r1 * K + (k0) + s1);            \
        CP16(SADDR(stg,1,r0,s0), gAl + (size_t)r0 * K + (k0) + s0);            \
        CP16(SADDR(stg,1,r1,s1), gAl + (size_t)r1 * K + (k0) + s1);            \
        CP16(SADDR(stg,2,r0,s0), gBh + (size_t)r0 * K + (k0) + s0);            \
        CP16(SADDR(stg,2,r1,s1), gBh + (size_t)r1 * K + (k0) + s1);            \
        CP16(SADDR(stg,3,r0,s0), gBl + (size_t)r0 * K + (k0) + s0);            \
        CP16(SADDR(stg,3,r1,s1), gBl + (size_t)r1 * K + (k0) + s1);            \
        COMMIT();                                                              \
    } while (0)

    LOAD_STAGE(0, 0);

    const int aRow  = (lane & 15);
    const int fBase = ((lane >> 4) << 3);

    for (int kt = 0; kt < nk; kt++) {
        const int buf = kt & 1;
        if (kt + 1 < nk) {
            LOAD_STAGE(buf ^ 1, (kt + 1) << 5);
            asm volatile("cp.async.wait_group 1;\n" ::);
        } else {
            asm volatile("cp.async.wait_group 0;\n" ::);
        }
        __syncthreads();

        #pragma unroll
        for (int ks = 0; ks < 2; ks++) {
            const int fcol = ks * 16 + fBase;
            uint32_t bh[2][4], bl[2][4];
            #pragma unroll
            for (int nt2 = 0; nt2 < 2; nt2++) {
                LDMX4(bh[nt2][0], bh[nt2][1], bh[nt2][2], bh[nt2][3],
                      SADDR(buf, 2, wn0 + nt2 * 16 + aRow, fcol));
                LDMX4(bl[nt2][0], bl[nt2][1], bl[nt2][2], bl[nt2][3],
                      SADDR(buf, 3, wn0 + nt2 * 16 + aRow, fcol));
            }
            #pragma unroll
            for (int mt = 0; mt < 4; mt++) {
                uint32_t a0, a1, a2, a3;
                LDMX4(a0, a1, a2, a3, SADDR(buf, 0, wm0 + mt * 16 + aRow, fcol));
                #pragma unroll
                for (int nt = 0; nt < 4; nt++)
                    MMA16816(acc[mt][nt], a0, a1, a2, a3,
                             bh[nt >> 1][nt & 1], bh[nt >> 1][(nt & 1) + 2]);
                #pragma unroll
                for (int nt = 0; nt < 4; nt++)
                    MMA16816(acc[mt][nt], a0, a1, a2, a3,
                             bl[nt >> 1][nt & 1], bl[nt >> 1][(nt & 1) + 2]);
                uint32_t c0, c1, c2, c3;
                LDMX4(c0, c1, c2, c3, SADDR(buf, 1, wm0 + mt * 16 + aRow, fcol));
                #pragma unroll
                for (int nt = 0; nt < 4; nt++)
                    MMA16816(acc[mt][nt], c0, c1, c2, c3,
                             bh[nt >> 1][nt & 1], bh[nt >> 1][(nt & 1) + 2]);
            }
        }
        __syncthreads();
    }

    // ---- epilogue ----
    const int g  = lane >> 2;
    const int tg = lane & 3;
    #pragma unroll
    for (int mt = 0; mt < 4; mt++) {
        #pragma unroll
        for (int nt = 0; nt < 4; nt++) {
            const int col = bn + wn0 + nt * 8 + tg * 2;
            const float bx = bias[col], by = bias[col + 1];
            #pragma unroll
            for (int hh = 0; hh < 2; hh++) {
                const int row = bm + wm0 + mt * 16 + g + hh * 8;
                float v0 = acc[mt][nt][hh * 2 + 0] + bx;
                float v1 = acc[mt][nt][hh * 2 + 1] + by;
                if (epi == 4) {
                    v0 = 0.5f * v0 * (1.0f + erff(v0 * 0.7071067811865475f));
                    v1 = 0.5f * v1 * (1.0f + erff(v1 * 0.7071067811865475f));
                }
                if (epi == 2) {
                    const float2 rv = *(const float2*)&R[(size_t)row * N + col];
                    v0 += rv.x; v1 += rv.y;
                    float2 o; o.x = v0; o.y = v1;
                    *(float2*)&C[(size_t)row * N + col] = o;
                } else {
                    __half2 hi = __floats2half2_rn(v0, v1);
                    *(__half2*)&Ch[(size_t)row * N + col] = hi;
                    if (epi == 4) {
                        float2 fh = __half22float2(hi);
                        __half2 lo = __floats2half2_rn(v0 - fh.x, v1 - fh.y);
                        *(__half2*)&Cl[(size_t)row * N + col] = lo;
                    }
                }
            }
        }
    }
}

// ---------------- tensor-core causal flash attention (fp16 in, fp32 accum) ----------------
// CTA: 128 threads (4 warps), 64 q-rows; warp = 16 rows. 64-key chunks, double-buffered.
// Output: hi/lo fp16 split of ctx, written directly.
#define QS 72   // smem row stride (halves)

__global__ __launch_bounds__(128) void attn_tc(const __half* __restrict__ QKVh,
                                               __half* __restrict__ Oh,
                                               __half* __restrict__ Ol) {
    __shared__ __half Qs[64][QS];
    __shared__ __half Ks[2][64][QS];
    __shared__ __half Vs[2][64][QS];

    const int bh = blockIdx.y;
    const int b  = bh >> 4;
    const int h  = bh & 15;
    const int q0 = blockIdx.x * 64;
    const int tid  = threadIdx.x;
    const int wq   = tid >> 5;
    const int lane = tid & 31;
    const int g  = lane >> 2;
    const int tg = lane & 3;

    const __half* Qg = QKVh + ((size_t)b * SEQ + q0) * QKVW + h * HDIM;
    const __half* Kg = QKVh + (size_t)b * SEQ * QKVW + DMODEL + h * HDIM;
    const __half* Vg = Kg + DMODEL;

    const uint32_t qB = (uint32_t)__cvta_generic_to_shared(&Qs[0][0]);
    const uint32_t kB = (uint32_t)__cvta_generic_to_shared(&Ks[0][0][0]);
    const uint32_t vB = (uint32_t)__cvta_generic_to_shared(&Vs[0][0][0]);
    const uint32_t bufStride = 64 * QS * 2;   // bytes per buffer

    // --- issue Q loads (group 0 part) + chunk 0 ---
    #pragma unroll
    for (int i = 0; i < 4; i++) {
        int idx = tid + i * 128;            // [0,512)
        int r = idx >> 3, sg = (idx & 7) * 8;
        CP16(qB + (r * QS + sg) * 2, Qg + (size_t)r * QKVW + sg);
    }
    #pragma unroll
    for (int i = 0; i < 4; i++) {
        int idx = tid + i * 128;
        int r = idx >> 3, sg = (idx & 7) * 8;
        CP16(kB + (r * QS + sg) * 2, Kg + (size_t)r * QKVW + sg);
        CP16(vB + (r * QS + sg) * 2, Vg + (size_t)r * QKVW + sg);
    }
    COMMIT();

    uint32_t Qa[4][4];
    float    o[8][4];
    #pragma unroll
    for (int i = 0; i < 8; i++)
        #pragma unroll
        for (int j = 0; j < 4; j++) o[i][j] = 0.f;
    float m0 = -1e30f, m1 = -1e30f, l0 = 0.f, l1 = 0.f;

    const int nchunks = (q0 >> 6) + 1;
    for (int it = 0; it < nchunks; it++) {
        const int buf = it & 1;
        if (it + 1 < nchunks) {
            const int c1 = (it + 1) << 6;
            #pragma unroll
            for (int i = 0; i < 4; i++) {
                int idx = tid + i * 128;
                int r = idx >> 3, sg = (idx & 7) * 8;
                CP16(kB + (buf ^ 1) * bufStride + (r * QS + sg) * 2, Kg + (size_t)(c1 + r) * QKVW + sg);
                CP16(vB + (buf ^ 1) * bufStride + (r * QS + sg) * 2, Vg + (size_t)(c1 + r) * QKVW + sg);
            }
            COMMIT();
            asm volatile("cp.async.wait_group 1;\n" ::);
        } else {
            asm volatile("cp.async.wait_group 0;\n" ::);
        }
        __syncthreads();

        if (it == 0) {
            // load Q fragments once (Q arrived with group 0)
            #pragma unroll
            for (int kk = 0; kk < 4; kk++) {
                uint32_t addr = qB + ((wq * 16 + (lane & 15)) * QS + kk * 16 + ((lane >> 4) << 3)) * 2;
                LDMX4(Qa[kk][0], Qa[kk][1], Qa[kk][2], Qa[kk][3], addr);
            }
        }

        // ---- S = Q K^T ----
        float s[8][4];
        #pragma unroll
        for (int i = 0; i < 8; i++)
            #pragma unroll
            for (int j = 0; j < 4; j++) s[i][j] = 0.f;

        #pragma unroll
        for (int kk = 0; kk < 4; kk++) {
            #pragma unroll
            for (int nt2 = 0; nt2 < 4; nt2++) {
                uint32_t r0, r1, r2, r3;
                uint32_t addr = kB + buf * bufStride +
                    ((nt2 * 16 + (lane & 15)) * QS + kk * 16 + ((lane >> 4) << 3)) * 2;
                LDMX4(r0, r1, r2, r3, addr);
                MMA16816(s[nt2 * 2],     Qa[kk][0], Qa[kk][1], Qa[kk][2], Qa[kk][3], r0, r2);
                MMA16816(s[nt2 * 2 + 1], Qa[kk][0], Qa[kk][1], Qa[kk][2], Qa[kk][3], r1, r3);
            }
        }

        // scale + causal mask (only the diagonal chunk)
        #pragma unroll
        for (int nt = 0; nt < 8; nt++)
            #pragma unroll
            for (int j = 0; j < 4; j++) s[nt][j] *= 0.125f;
        if (it == nchunks - 1) {
            const int row0 = wq * 16 + g, row1 = row0 + 8;
            #pragma unroll
            for (int nt = 0; nt < 8; nt++) {
                const int cb = nt * 8 + 2 * tg;
                if (cb     > row0) s[nt][0] = -1e30f;
                if (cb + 1 > row0) s[nt][1] = -1e30f;
                if (cb     > row1) s[nt][2] = -1e30f;
                if (cb + 1 > row1) s[nt][3] = -1e30f;
            }
        }

        // ---- online softmax ----
        float mx0 = -1e30f, mx1 = -1e30f;
        #pragma unroll
        for (int nt = 0; nt < 8; nt++) {
            mx0 = fmaxf(mx0, fmaxf(s[nt][0], s[nt][1]));
            mx1 = fmaxf(mx1, fmaxf(s[nt][2], s[nt][3]));
        }
        mx0 = fmaxf(mx0, __shfl_xor_sync(0xffffffffu, mx0, 1));
        mx0 = fmaxf(mx0, __shfl_xor_sync(0xffffffffu, mx0, 2));
        mx1 = fmaxf(mx1, __shfl_xor_sync(0xffffffffu, mx1, 1));
        mx1 = fmaxf(mx1, __shfl_xor_sync(0xffffffffu, mx1, 2));
        const float mn0 = fmaxf(m0, mx0), mn1 = fmaxf(m1, mx1);
        const float cr0 = __expf(m0 - mn0), cr1 = __expf(m1 - mn1);
        float ps0 = 0.f, ps1 = 0.f;
        #pragma unroll
        for (int nt = 0; nt < 8; nt++) {
            s[nt][0] = __expf(s[nt][0] - mn0);
            s[nt][1] = __expf(s[nt][1] - mn0);
            s[nt][2] = __expf(s[nt][2] - mn1);
            s[nt][3] = __expf(s[nt][3] - mn1);
            ps0 += s[nt][0] + s[nt][1];
            ps1 += s[nt][2] + s[nt][3];
        }
        ps0 += __shfl_xor_sync(0xffffffffu, ps0, 1);
        ps0 += __shfl_xor_sync(0xffffffffu, ps0, 2);
        ps1 += __shfl_xor_sync(0xffffffffu, ps1, 1);
        ps1 += __shfl_xor_sync(0xffffffffu, ps1, 2);
        l0 = l0 * cr0 + ps0;
        l1 = l1 * cr1 + ps1;
        m0 = mn0; m1 = mn1;
        #pragma unroll
        for (int nd = 0; nd < 8; nd++) {
            o[nd][0] *= cr0; o[nd][1] *= cr0;
            o[nd][2] *= cr1; o[nd][3] *= cr1;
        }

        // ---- O += P V ----
        #pragma unroll
        for (int kk = 0; kk < 4; kk++) {
            __half2 t0 = __floats2half2_rn(s[2*kk][0],   s[2*kk][1]);
            __half2 t1 = __floats2half2_rn(s[2*kk][2],   s[2*kk][3]);
            __half2 t2 = __floats2half2_rn(s[2*kk+1][0], s[2*kk+1][1]);
            __half2 t3 = __floats2half2_rn(s[2*kk+1][2], s[2*kk+1][3]);
            uint32_t pa0 = *(uint32_t*)&t0, pa1 = *(uint32_t*)&t1;
            uint32_t pa2 = *(uint32_t*)&t2, pa3 = *(uint32_t*)&t3;
            #pragma unroll
            for (int nd2 = 0; nd2 < 4; nd2++) {
                uint32_t r0, r1, r2, r3;
                uint32_t addr = vB + buf * bufStride +
                    ((kk * 16 + (lane & 15)) * QS + nd2 * 16 + ((lane >> 4) << 3)) * 2;
                LDMX4T(r0, r1, r2, r3, addr);
                MMA16816(o[nd2 * 2],     pa0, pa1, pa2, pa3, r0, r1);
                MMA16816(o[nd2 * 2 + 1], pa0, pa1, pa2, pa3, r2, r3);
            }
        }
        __syncthreads();
    }

    // ---- epilogue: normalize, hi/lo split, write ----
    const float inv0 = 1.f / l0, inv1 = 1.f / l1;
    const int row0 = q0 + wq * 16 + g;
    const size_t ob0 = ((size_t)b * SEQ + row0) * DMODEL + h * HDIM;
    const size_t ob1 = ob0 + 8 * DMODEL;
    #pragma unroll
    for (int nd = 0; nd < 8; nd++) {
        const int d = nd * 8 + 2 * tg;
        float v0 = o[nd][0] * inv0, v1 = o[nd][1] * inv0;
        __half2 hi = __floats2half2_rn(v0, v1);
        float2 fh = __half22float2(hi);
        __half2 lo = __floats2half2_rn(v0 - fh.x, v1 - fh.y);
        *(__half2*)&Oh[ob0 + d] = hi;
        *(__half2*)&Ol[ob0 + d] = lo;
        v0 = o[nd][2] * inv1; v1 = o[nd][3] * inv1;
        hi = __floats2half2_rn(v0, v1);
        fh = __half22float2(hi);
        lo = __floats2half2_rn(v0 - fh.x, v1 - fh.y);
        *(__half2*)&Oh[ob1 + d] = hi;
        *(__half2*)&Ol[ob1 + d] = lo;
    }
}

// ---------------- launcher ----------------
extern "C" void kernel_launch(void* const* d_in, const int* in_sizes, int n_in,
                              void* d_out, int out_size) {
    const float* x     = (const float*)d_in[0];
    const float* Wq    = (const float*)d_in[2];
    const float* bq    = (const float*)d_in[3];
    const float* Wk    = (const float*)d_in[4];
    const float* bk    = (const float*)d_in[5];
    const float* Wv    = (const float*)d_in[6];
    const float* bv    = (const float*)d_in[7];
    const float* Wo    = (const float*)d_in[8];
    const float* bo    = (const float*)d_in[9];
    const float* W1    = (const float*)d_in[10];
    const float* b1    = (const float*)d_in[11];
    const float* W2    = (const float*)d_in[12];
    const float* b2    = (const float*)d_in[13];
    const float* g1    = (const float*)d_in[14];
    const float* beta1 = (const float*)d_in[15];
    const float* g2    = (const float*)d_in[16];
    const float* beta2 = (const float*)d_in[17];
    float* out = (float*)d_out;

    float *x2, *bqkv;
    __half *qkvh, *ah, *al, *hh, *hl, *wh, *wl;
    cudaGetSymbolAddress((void**)&x2,   g_x2);
    cudaGetSymbolAddress((void**)&bqkv, g_bqkv);
    cudaGetSymbolAddress((void**)&qkvh, g_qkvh);
    cudaGetSymbolAddress((void**)&ah,   g_ah);
    cudaGetSymbolAddress((void**)&al,   g_al);
    cudaGetSymbolAddress((void**)&hh,   g_hh);
    cudaGetSymbolAddress((void**)&hl,   g_hl);
    cudaGetSymbolAddress((void**)&wh,   g_wh);
    cudaGetSymbolAddress((void**)&wl,   g_wl);

    static bool attr_set = false;
    if (!attr_set) {
        cudaFuncSetAttribute(hgemm3, cudaFuncAttributeMaxDynamicSharedMemorySize, GSMEM_BYTES);
        attr_set = true;
    }

    const int M = MROWS, D = DMODEL, F = FFDIM;
    const size_t DD = (size_t)D * D;

    // LN1 -> fp16 splits
    ln_split<<<M, 256>>>(x, g1, beta1, ah, al);

    // fused QKV GEMM -> fp16 output
    split2<<<(int)(DD / 2) / 256, 256>>>(Wq, wh, wl);
    split2<<<(int)(DD / 2) / 256, 256>>>(Wk, wh + DD, wl + DD);
    split2<<<(int)(DD / 2) / 256, 256>>>(Wv, wh + 2 * DD, wl + 2 * DD);
    pack_bias<<<QKVW / 256, 256>>>(bq, bk, bv, bqkv);
    dim3 gQKV(QKVW / 128, M / 128);
    hgemm3<<<gQKV, 256, GSMEM_BYTES>>>(ah, al, wh, wl, bqkv, nullptr,
                                       nullptr, qkvh, nullptr, M, QKVW, D, 3);

    // tensor-core causal attention -> ctx hi/lo splits
    dim3 gA(SEQ / 64, BSZ * NHEADS);
    attn_tc<<<gA, 128>>>(qkvh, ah, al);

    // output projection + residual -> x2 (fp32)
    split2<<<(int)(DD / 2) / 256, 256>>>(Wo, wh, wl);
    dim3 gD(D / 128, M / 128);
    hgemm3<<<gD, 256, GSMEM_BYTES>>>(ah, al, wh, wl, bo, x,
                                     x2, nullptr, nullptr, M, D, D, 2);

    // LN2 -> fp16 splits
    ln_split<<<M, 256>>>(x2, g2, beta2, ah, al);

    // FFN1 (GELU) -> hidden hi/lo splits
    split2<<<(int)((size_t)F * D / 2) / 256, 256>>>(W1, wh, wl);
    dim3 gF1(F / 128, M / 128);
    hgemm3<<<gF1, 256, GSMEM_BYTES>>>(ah, al, wh, wl, b1, nullptr,
                                      nullptr, hh, hl, M, F, D, 4);

    // FFN2 + residual -> out (fp32)
    split2<<<(int)((size_t)D * F / 2) / 256, 256>>>(W2, wh, wl);
    hgemm3<<<gD, 256, GSMEM_BYTES>>>(hh, hl, wh, wl, b2, x2,
                                     out, nullptr, nullptr, M, D, F, 2);
}

// round 6
// speedup vs baseline: 4.0567x; 1.4130x over previous
#include <cuda_runtime.h>
#include <cuda_fp16.h>
#include <math.h>
#include <stdint.h>

// ---------------- problem constants ----------------
#define BSZ    2
#define SEQ    2048
#define DMODEL 1024
#define NHEADS 16
#define HDIM   64
#define FFDIM  4096
#define MROWS (BSZ*SEQ)          // 4096
#define QKVW  (3*DMODEL)         // 3072
#define LN_EPS 1e-5f

// ---------------- scratch (device globals; no allocs) ----------------
__device__ float  g_x2  [MROWS*DMODEL];
__device__ float  g_bqkv[QKVW];
__device__ __half g_qkvh[(size_t)MROWS*QKVW];
__device__ __half g_ah[(size_t)MROWS*DMODEL];    // activations (fp16)
__device__ __half g_hh[(size_t)MROWS*FFDIM];     // FFN hidden (fp16)
__device__ __half g_wh[(size_t)FFDIM*DMODEL];    // weight hi
__device__ __half g_wl[(size_t)FFDIM*DMODEL];    // weight lo

// ---------------- LayerNorm -> fp16 directly ----------------
__global__ __launch_bounds__(256) void ln_h16(const float* __restrict__ x,
                                              const float* __restrict__ g,
                                              const float* __restrict__ b,
                                              __half* __restrict__ ah) {
    int row = blockIdx.x;
    int t   = threadIdx.x;
    const float4 v = ((const float4*)(x + (size_t)row * DMODEL))[t];
    float s  = v.x + v.y + v.z + v.w;
    float ss = v.x*v.x + v.y*v.y + v.z*v.z + v.w*v.w;
    #pragma unroll
    for (int o = 16; o; o >>= 1) {
        s  += __shfl_xor_sync(0xffffffffu, s,  o);
        ss += __shfl_xor_sync(0xffffffffu, ss, o);
    }
    __shared__ float rs[8], rss[8];
    if ((t & 31) == 0) { rs[t >> 5] = s; rss[t >> 5] = ss; }
    __syncthreads();
    float S = 0.f, SS = 0.f;
    #pragma unroll
    for (int i = 0; i < 8; i++) { S += rs[i]; SS += rss[i]; }
    float mean = S * (1.f / DMODEL);
    float var  = SS * (1.f / DMODEL) - mean * mean;
    float rstd = rsqrtf(var + LN_EPS);
    const float4 gv = ((const float4*)g)[t];
    const float4 bv = ((const float4*)b)[t];
    float o0 = (v.x - mean) * rstd * gv.x + bv.x;
    float o1 = (v.y - mean) * rstd * gv.y + bv.y;
    float o2 = (v.z - mean) * rstd * gv.z + bv.z;
    float o3 = (v.w - mean) * rstd * gv.w + bv.w;
    __half2* ph = (__half2*)(ah + (size_t)row * DMODEL);
    ph[t*2]   = __floats2half2_rn(o0, o1);
    ph[t*2+1] = __floats2half2_rn(o2, o3);
}

// ---------------- fp32 -> (hi, lo) fp16 split (weights) ----------------
__global__ __launch_bounds__(256) void split2(const float* __restrict__ src,
                                              __half* __restrict__ dh,
                                              __half* __restrict__ dl) {
    size_t i = ((size_t)blockIdx.x * 256 + threadIdx.x) * 2;
    float2 f = *(const float2*)(src + i);
    __half2 hi = __floats2half2_rn(f.x, f.y);
    float2 fh = __half22float2(hi);
    __half2 lo = __floats2half2_rn(f.x - fh.x, f.y - fh.y);
    *(__half2*)(dh + i) = hi;
    *(__half2*)(dl + i) = lo;
}

__global__ void pack_bias(const float* __restrict__ a, const float* __restrict__ b,
                          const float* __restrict__ c, float* __restrict__ out) {
    int i = blockIdx.x * 256 + threadIdx.x;
    float v = (i < 1024) ? a[i] : (i < 2048) ? b[i - 1024] : c[i - 2048];
    out[i] = v;
}

// ---------------- PTX helpers ----------------
#define CP16(sa, ga) asm volatile("cp.async.cg.shared.global [%0], [%1], 16;\n" :: "r"(sa), "l"(ga))
#define COMMIT() asm volatile("cp.async.commit_group;\n" ::)
#define LDMX4(r0,r1,r2,r3,addr) asm volatile( \
    "ldmatrix.sync.aligned.m8n8.x4.shared.b16 {%0,%1,%2,%3}, [%4];" \
    : "=r"(r0), "=r"(r1), "=r"(r2), "=r"(r3) : "r"(addr))
#define LDMX4T(r0,r1,r2,r3,addr) asm volatile( \
    "ldmatrix.sync.aligned.m8n8.x4.trans.shared.b16 {%0,%1,%2,%3}, [%4];" \
    : "=r"(r0), "=r"(r1), "=r"(r2), "=r"(r3) : "r"(addr))
#define MMA16816(d, a0,a1,a2,a3, b0,b1) asm volatile( \
    "mma.sync.aligned.m16n8k16.row.col.f32.f16.f16.f32 " \
    "{%0,%1,%2,%3}, {%4,%5,%6,%7}, {%8,%9}, {%0,%1,%2,%3};" \
    : "+f"(d[0]), "+f"(d[1]), "+f"(d[2]), "+f"(d[3]) \
    : "r"(a0), "r"(a1), "r"(a2), "r"(a3), "r"(b0), "r"(b1))

// ---------------- compensated fp16 GEMM (2-term, 3-stage pipeline) ----------------
// C[M,N] = Ah[M,K] @ (Bh+Bl)[N,K]^T
// epi: 2 = bias+residual -> float C ; 3 = bias -> half Ch ; 4 = bias+GELU -> half Ch
#define TILE_H  (128 * 40)          // halves per 128x32 tile (stride 40)
#define STAGE_H (3 * TILE_H)        // Ah, Bh, Bl
#define GSMEM_BYTES (3 * STAGE_H * 2)

__global__ __launch_bounds__(256, 2) void hgemm2t(const __half* __restrict__ Ah,
                                                  const __half* __restrict__ Bh,
                                                  const __half* __restrict__ Bl,
                                                  const float* __restrict__ bias,
                                                  const float* __restrict__ R,
                                                  float* __restrict__ C,
                                                  __half* __restrict__ Ch,
                                                  int M, int N, int K, int epi) {
    extern __shared__ __half sm16[];

    const int tid  = threadIdx.x;
    const int wid  = tid >> 5;
    const int lane = tid & 31;
    const int bm   = blockIdx.y * 128;
    const int bn   = blockIdx.x * 128;
    const int wm0  = (wid >> 2) * 64;
    const int wn0  = (wid & 3) * 32;

    float acc[4][4][4];
    #pragma unroll
    for (int i = 0; i < 4; i++)
        #pragma unroll
        for (int j = 0; j < 4; j++)
            #pragma unroll
            for (int t = 0; t < 4; t++) acc[i][j][t] = 0.f;

    const int nk = K >> 5;
    const int r0 = tid >> 2,         s0 = (tid & 3) * 8;
    const int r1 = (tid + 256) >> 2, s1 = ((tid + 256) & 3) * 8;

    const uint32_t smBase = (uint32_t)__cvta_generic_to_shared(sm16);
    #define SADDR(stage, tile, row, col) (smBase + (((stage)*STAGE_H + (tile)*TILE_H + (row)*40 + (col)) << 1))

    const __half* gAh = Ah + (size_t)bm * K;
    const __half* gBh = Bh + (size_t)bn * K;
    const __half* gBl = Bl + (size_t)bn * K;

    #define LOAD_STAGE(stg, k0)  do {                                          \
        CP16(SADDR(stg,0,r0,s0), gAh + (size_t)r0 * K + (k0) + s0);            \
        CP16(SADDR(stg,0,r1,s1), gAh + (size_t)r1 * K + (k0) + s1);            \
        CP16(SADDR(stg,1,r0,s0), gBh + (size_t)r0 * K + (k0) + s0);            \
        CP16(SADDR(stg,1,r1,s1), gBh + (size_t)r1 * K + (k0) + s1);            \
        CP16(SADDR(stg,2,r0,s0), gBl + (size_t)r0 * K + (k0) + s0);            \
        CP16(SADDR(stg,2,r1,s1), gBl + (size_t)r1 * K + (k0) + s1);            \
        COMMIT();                                                              \
    } while (0)

    LOAD_STAGE(0, 0);
    LOAD_STAGE(1, 32);

    const int aRow  = (lane & 15);
    const int fBase = ((lane >> 4) << 3);

    for (int kt = 0; kt < nk; kt++) {
        const int buf = kt % 3;
        if (kt + 1 < nk) {
            asm volatile("cp.async.wait_group 1;\n" ::);
        } else {
            asm volatile("cp.async.wait_group 0;\n" ::);
        }
        __syncthreads();

        #pragma unroll
        for (int ks = 0; ks < 2; ks++) {
            const int fcol = ks * 16 + fBase;
            uint32_t bh[2][4], bl[2][4];
            #pragma unroll
            for (int nt2 = 0; nt2 < 2; nt2++) {
                LDMX4(bh[nt2][0], bh[nt2][1], bh[nt2][2], bh[nt2][3],
                      SADDR(buf, 1, wn0 + nt2 * 16 + aRow, fcol));
                LDMX4(bl[nt2][0], bl[nt2][1], bl[nt2][2], bl[nt2][3],
                      SADDR(buf, 2, wn0 + nt2 * 16 + aRow, fcol));
            }
            #pragma unroll
            for (int mt = 0; mt < 4; mt++) {
                uint32_t a0, a1, a2, a3;
                LDMX4(a0, a1, a2, a3, SADDR(buf, 0, wm0 + mt * 16 + aRow, fcol));
                #pragma unroll
                for (int nt = 0; nt < 4; nt++)
                    MMA16816(acc[mt][nt], a0, a1, a2, a3,
                             bh[nt >> 1][nt & 1], bh[nt >> 1][(nt & 1) + 2]);
                #pragma unroll
                for (int nt = 0; nt < 4; nt++)
                    MMA16816(acc[mt][nt], a0, a1, a2, a3,
                             bl[nt >> 1][nt & 1], bl[nt >> 1][(nt & 1) + 2]);
            }
        }

        if (kt + 2 < nk) {
            LOAD_STAGE((kt + 2) % 3, (kt + 2) << 5);
        }
    }

    // ---- epilogue ----
    const int g  = lane >> 2;
    const int tg = lane & 3;
    #pragma unroll
    for (int mt = 0; mt < 4; mt++) {
        #pragma unroll
        for (int nt = 0; nt < 4; nt++) {
            const int col = bn + wn0 + nt * 8 + tg * 2;
            const float bx = bias[col], by = bias[col + 1];
            #pragma unroll
            for (int hh = 0; hh < 2; hh++) {
                const int row = bm + wm0 + mt * 16 + g + hh * 8;
                float v0 = acc[mt][nt][hh * 2 + 0] + bx;
                float v1 = acc[mt][nt][hh * 2 + 1] + by;
                if (epi == 4) {
                    v0 = 0.5f * v0 * (1.0f + erff(v0 * 0.7071067811865475f));
                    v1 = 0.5f * v1 * (1.0f + erff(v1 * 0.7071067811865475f));
                }
                if (epi == 2) {
                    const float2 rv = *(const float2*)&R[(size_t)row * N + col];
                    v0 += rv.x; v1 += rv.y;
                    float2 o; o.x = v0; o.y = v1;
                    *(float2*)&C[(size_t)row * N + col] = o;
                } else {
                    *(__half2*)&Ch[(size_t)row * N + col] = __floats2half2_rn(v0, v1);
                }
            }
        }
    }
}

// ---------------- tensor-core causal flash attention (fp16 in, fp32 accum) ----------------
#define QS 72

__global__ __launch_bounds__(128) void attn_tc(const __half* __restrict__ QKVh,
                                               __half* __restrict__ Oh) {
    __shared__ __half Qs[64][QS];
    __shared__ __half Ks[2][64][QS];
    __shared__ __half Vs[2][64][QS];

    const int bh = blockIdx.y;
    const int b  = bh >> 4;
    const int h  = bh & 15;
    const int q0 = blockIdx.x * 64;
    const int tid  = threadIdx.x;
    const int wq   = tid >> 5;
    const int lane = tid & 31;
    const int g  = lane >> 2;
    const int tg = lane & 3;

    const __half* Qg = QKVh + ((size_t)b * SEQ + q0) * QKVW + h * HDIM;
    const __half* Kg = QKVh + (size_t)b * SEQ * QKVW + DMODEL + h * HDIM;
    const __half* Vg = Kg + DMODEL;

    const uint32_t qB = (uint32_t)__cvta_generic_to_shared(&Qs[0][0]);
    const uint32_t kB = (uint32_t)__cvta_generic_to_shared(&Ks[0][0][0]);
    const uint32_t vB = (uint32_t)__cvta_generic_to_shared(&Vs[0][0][0]);
    const uint32_t bufStride = 64 * QS * 2;

    #pragma unroll
    for (int i = 0; i < 4; i++) {
        int idx = tid + i * 128;
        int r = idx >> 3, sg = (idx & 7) * 8;
        CP16(qB + (r * QS + sg) * 2, Qg + (size_t)r * QKVW + sg);
    }
    #pragma unroll
    for (int i = 0; i < 4; i++) {
        int idx = tid + i * 128;
        int r = idx >> 3, sg = (idx & 7) * 8;
        CP16(kB + (r * QS + sg) * 2, Kg + (size_t)r * QKVW + sg);
        CP16(vB + (r * QS + sg) * 2, Vg + (size_t)r * QKVW + sg);
    }
    COMMIT();

    uint32_t Qa[4][4];
    float    o[8][4];
    #pragma unroll
    for (int i = 0; i < 8; i++)
        #pragma unroll
        for (int j = 0; j < 4; j++) o[i][j] = 0.f;
    float m0 = -1e30f, m1 = -1e30f, l0 = 0.f, l1 = 0.f;

    const int nchunks = (q0 >> 6) + 1;
    for (int it = 0; it < nchunks; it++) {
        const int buf = it & 1;
        if (it + 1 < nchunks) {
            const int c1 = (it + 1) << 6;
            #pragma unroll
            for (int i = 0; i < 4; i++) {
                int idx = tid + i * 128;
                int r = idx >> 3, sg = (idx & 7) * 8;
                CP16(kB + (buf ^ 1) * bufStride + (r * QS + sg) * 2, Kg + (size_t)(c1 + r) * QKVW + sg);
                CP16(vB + (buf ^ 1) * bufStride + (r * QS + sg) * 2, Vg + (size_t)(c1 + r) * QKVW + sg);
            }
            COMMIT();
            asm volatile("cp.async.wait_group 1;\n" ::);
        } else {
            asm volatile("cp.async.wait_group 0;\n" ::);
        }
        __syncthreads();

        if (it == 0) {
            #pragma unroll
            for (int kk = 0; kk < 4; kk++) {
                uint32_t addr = qB + ((wq * 16 + (lane & 15)) * QS + kk * 16 + ((lane >> 4) << 3)) * 2;
                LDMX4(Qa[kk][0], Qa[kk][1], Qa[kk][2], Qa[kk][3], addr);
            }
        }

        float s[8][4];
        #pragma unroll
        for (int i = 0; i < 8; i++)
            #pragma unroll
            for (int j = 0; j < 4; j++) s[i][j] = 0.f;

        #pragma unroll
        for (int kk = 0; kk < 4; kk++) {
            #pragma unroll
            for (int nt2 = 0; nt2 < 4; nt2++) {
                uint32_t r0, r1, r2, r3;
                uint32_t addr = kB + buf * bufStride +
                    ((nt2 * 16 + (lane & 15)) * QS + kk * 16 + ((lane >> 4) << 3)) * 2;
                LDMX4(r0, r1, r2, r3, addr);
                MMA16816(s[nt2 * 2],     Qa[kk][0], Qa[kk][1], Qa[kk][2], Qa[kk][3], r0, r2);
                MMA16816(s[nt2 * 2 + 1], Qa[kk][0], Qa[kk][1], Qa[kk][2], Qa[kk][3], r1, r3);
            }
        }

        #pragma unroll
        for (int nt = 0; nt < 8; nt++)
            #pragma unroll
            for (int j = 0; j < 4; j++) s[nt][j] *= 0.125f;
        if (it == nchunks - 1) {
            const int row0 = wq * 16 + g, row1 = row0 + 8;
            #pragma unroll
            for (int nt = 0; nt < 8; nt++) {
                const int cb = nt * 8 + 2 * tg;
                if (cb     > row0) s[nt][0] = -1e30f;
                if (cb + 1 > row0) s[nt][1] = -1e30f;
                if (cb     > row1) s[nt][2] = -1e30f;
                if (cb + 1 > row1) s[nt][3] = -1e30f;
            }
        }

        float mx0 = -1e30f, mx1 = -1e30f;
        #pragma unroll
        for (int nt = 0; nt < 8; nt++) {
            mx0 = fmaxf(mx0, fmaxf(s[nt][0], s[nt][1]));
            mx1 = fmaxf(mx1, fmaxf(s[nt][2], s[nt][3]));
        }
        mx0 = fmaxf(mx0, __shfl_xor_sync(0xffffffffu, mx0, 1));
        mx0 = fmaxf(mx0, __shfl_xor_sync(0xffffffffu, mx0, 2));
        mx1 = fmaxf(mx1, __shfl_xor_sync(0xffffffffu, mx1, 1));
        mx1 = fmaxf(mx1, __shfl_xor_sync(0xffffffffu, mx1, 2));
        const float mn0 = fmaxf(m0, mx0), mn1 = fmaxf(m1, mx1);
        const float cr0 = __expf(m0 - mn0), cr1 = __expf(m1 - mn1);
        float ps0 = 0.f, ps1 = 0.f;
        #pragma unroll
        for (int nt = 0; nt < 8; nt++) {
            s[nt][0] = __expf(s[nt][0] - mn0);
            s[nt][1] = __expf(s[nt][1] - mn0);
            s[nt][2] = __expf(s[nt][2] - mn1);
            s[nt][3] = __expf(s[nt][3] - mn1);
            ps0 += s[nt][0] + s[nt][1];
            ps1 += s[nt][2] + s[nt][3];
        }
        ps0 += __shfl_xor_sync(0xffffffffu, ps0, 1);
        ps0 += __shfl_xor_sync(0xffffffffu, ps0, 2);
        ps1 += __shfl_xor_sync(0xffffffffu, ps1, 1);
        ps1 += __shfl_xor_sync(0xffffffffu, ps1, 2);
        l0 = l0 * cr0 + ps0;
        l1 = l1 * cr1 + ps1;
        m0 = mn0; m1 = mn1;
        #pragma unroll
        for (int nd = 0; nd < 8; nd++) {
            o[nd][0] *= cr0; o[nd][1] *= cr0;
            o[nd][2] *= cr1; o[nd][3] *= cr1;
        }

        #pragma unroll
        for (int kk = 0; kk < 4; kk++) {
            __half2 t0 = __floats2half2_rn(s[2*kk][0],   s[2*kk][1]);
            __half2 t1 = __floats2half2_rn(s[2*kk][2],   s[2*kk][3]);
            __half2 t2 = __floats2half2_rn(s[2*kk+1][0], s[2*kk+1][1]);
            __half2 t3 = __floats2half2_rn(s[2*kk+1][2], s[2*kk+1][3]);
            uint32_t pa0 = *(uint32_t*)&t0, pa1 = *(uint32_t*)&t1;
            uint32_t pa2 = *(uint32_t*)&t2, pa3 = *(uint32_t*)&t3;
            #pragma unroll
            for (int nd2 = 0; nd2 < 4; nd2++) {
                uint32_t r0, r1, r2, r3;
                uint32_t addr = vB + buf * bufStride +
                    ((kk * 16 + (lane & 15)) * QS + nd2 * 16 + ((lane >> 4) << 3)) * 2;
                LDMX4T(r0, r1, r2, r3, addr);
                MMA16816(o[nd2 * 2],     pa0, pa1, pa2, pa3, r0, r1);
                MMA16816(o[nd2 * 2 + 1], pa0, pa1, pa2, pa3, r2, r3);
            }
        }
        __syncthreads();
    }

    const float inv0 = 1.f / l0, inv1 = 1.f / l1;
    const int row0 = q0 + wq * 16 + g;
    const size_t ob0 = ((size_t)b * SEQ + row0) * DMODEL + h * HDIM;
    const size_t ob1 = ob0 + 8 * DMODEL;
    #pragma unroll
    for (int nd = 0; nd < 8; nd++) {
        const int d = nd * 8 + 2 * tg;
        *(__half2*)&Oh[ob0 + d] = __floats2half2_rn(o[nd][0] * inv0, o[nd][1] * inv0);
        *(__half2*)&Oh[ob1 + d] = __floats2half2_rn(o[nd][2] * inv1, o[nd][3] * inv1);
    }
}

// ---------------- launcher ----------------
extern "C" void kernel_launch(void* const* d_in, const int* in_sizes, int n_in,
                              void* d_out, int out_size) {
    const float* x     = (const float*)d_in[0];
    const float* Wq    = (const float*)d_in[2];
    const float* bq    = (const float*)d_in[3];
    const float* Wk    = (const float*)d_in[4];
    const float* bk    = (const float*)d_in[5];
    const float* Wv    = (const float*)d_in[6];
    const float* bv    = (const float*)d_in[7];
    const float* Wo    = (const float*)d_in[8];
    const float* bo    = (const float*)d_in[9];
    const float* W1    = (const float*)d_in[10];
    const float* b1    = (const float*)d_in[11];
    const float* W2    = (const float*)d_in[12];
    const float* b2    = (const float*)d_in[13];
    const float* g1    = (const float*)d_in[14];
    const float* beta1 = (const float*)d_in[15];
    const float* g2    = (const float*)d_in[16];
    const float* beta2 = (const float*)d_in[17];
    float* out = (float*)d_out;

    float *x2, *bqkv;
    __half *qkvh, *ah, *hh, *wh, *wl;
    cudaGetSymbolAddress((void**)&x2,   g_x2);
    cudaGetSymbolAddress((void**)&bqkv, g_bqkv);
    cudaGetSymbolAddress((void**)&qkvh, g_qkvh);
    cudaGetSymbolAddress((void**)&ah,   g_ah);
    cudaGetSymbolAddress((void**)&hh,   g_hh);
    cudaGetSymbolAddress((void**)&wh,   g_wh);
    cudaGetSymbolAddress((void**)&wl,   g_wl);

    static bool attr_set = false;
    if (!attr_set) {
        cudaFuncSetAttribute(hgemm2t, cudaFuncAttributeMaxDynamicSharedMemorySize, GSMEM_BYTES);
        attr_set = true;
    }

    const int M = MROWS, D = DMODEL, F = FFDIM;
    const size_t DD = (size_t)D * D;

    // LN1 -> fp16
    ln_h16<<<M, 256>>>(x, g1, beta1, ah);

    // fused QKV GEMM -> fp16 output (N = 3072)
    split2<<<(int)(DD / 2) / 256, 256>>>(Wq, wh, wl);
    split2<<<(int)(DD / 2) / 256, 256>>>(Wk, wh + DD, wl + DD);
    split2<<<(int)(DD / 2) / 256, 256>>>(Wv, wh + 2 * DD, wl + 2 * DD);
    pack_bias<<<QKVW / 256, 256>>>(bq, bk, bv, bqkv);
    dim3 gQKV(QKVW / 128, M / 128);
    hgemm2t<<<gQKV, 256, GSMEM_BYTES>>>(ah, wh, wl, bqkv, nullptr,
                                        nullptr, qkvh, M, QKVW, D, 3);

    // tensor-core causal attention -> ctx fp16
    dim3 gA(SEQ / 64, BSZ * NHEADS);
    attn_tc<<<gA, 128>>>(qkvh, ah);

    // output projection + residual -> x2 (fp32)
    split2<<<(int)(DD / 2) / 256, 256>>>(Wo, wh, wl);
    dim3 gD(D / 128, M / 128);
    hgemm2t<<<gD, 256, GSMEM_BYTES>>>(ah, wh, wl, bo, x,
                                      x2, nullptr, M, D, D, 2);

    // LN2 -> fp16
    ln_h16<<<M, 256>>>(x2, g2, beta2, ah);

    // FFN1 (GELU) -> hidden fp16 (N = 4096)
    split2<<<(int)((size_t)F * D / 2) / 256, 256>>>(W1, wh, wl);
    dim3 gF1(F / 128, M / 128);
    hgemm2t<<<gF1, 256, GSMEM_BYTES>>>(ah, wh, wl, b1, nullptr,
                                       nullptr, hh, M, F, D, 4);

    // FFN2 + residual -> out (fp32), K = 4096
    split2<<<(int)((size_t)D * F / 2) / 256, 256>>>(W2, wh, wl);
    hgemm2t<<<gD, 256, GSMEM_BYTES>>>(hh, wh, wl, b2, x2,
                                      out, nullptr, M, D, F, 2);
}

// round 7
// speedup vs baseline: 4.1567x; 1.0247x over previous
#include <cuda_runtime.h>
#include <cuda_fp16.h>
#include <math.h>
#include <stdint.h>

// ---------------- problem constants ----------------
#define BSZ    2
#define SEQ    2048
#define DMODEL 1024
#define NHEADS 16
#define HDIM   64
#define FFDIM  4096
#define MROWS (BSZ*SEQ)          // 4096
#define QKVW  (3*DMODEL)         // 3072
#define LN_EPS 1e-5f

// ---------------- scratch (device globals; no allocs) ----------------
__device__ float  g_x2  [MROWS*DMODEL];
__device__ float  g_bqkv[QKVW];
__device__ __half g_qkvh[(size_t)MROWS*QKVW];
__device__ __half g_ah[(size_t)MROWS*DMODEL];    // activations (fp16)
__device__ __half g_hh[(size_t)MROWS*FFDIM];     // FFN hidden (fp16)
__device__ __half g_wh[(size_t)FFDIM*DMODEL];    // weight hi
__device__ __half g_wl[(size_t)FFDIM*DMODEL];    // weight lo

// ---------------- LayerNorm -> fp16 directly ----------------
__global__ __launch_bounds__(256) void ln_h16(const float* __restrict__ x,
                                              const float* __restrict__ g,
                                              const float* __restrict__ b,
                                              __half* __restrict__ ah) {
    int row = blockIdx.x;
    int t   = threadIdx.x;
    const float4 v = ((const float4*)(x + (size_t)row * DMODEL))[t];
    float s  = v.x + v.y + v.z + v.w;
    float ss = v.x*v.x + v.y*v.y + v.z*v.z + v.w*v.w;
    #pragma unroll
    for (int o = 16; o; o >>= 1) {
        s  += __shfl_xor_sync(0xffffffffu, s,  o);
        ss += __shfl_xor_sync(0xffffffffu, ss, o);
    }
    __shared__ float rs[8], rss[8];
    if ((t & 31) == 0) { rs[t >> 5] = s; rss[t >> 5] = ss; }
    __syncthreads();
    float S = 0.f, SS = 0.f;
    #pragma unroll
    for (int i = 0; i < 8; i++) { S += rs[i]; SS += rss[i]; }
    float mean = S * (1.f / DMODEL);
    float var  = SS * (1.f / DMODEL) - mean * mean;
    float rstd = rsqrtf(var + LN_EPS);
    const float4 gv = ((const float4*)g)[t];
    const float4 bv = ((const float4*)b)[t];
    float o0 = (v.x - mean) * rstd * gv.x + bv.x;
    float o1 = (v.y - mean) * rstd * gv.y + bv.y;
    float o2 = (v.z - mean) * rstd * gv.z + bv.z;
    float o3 = (v.w - mean) * rstd * gv.w + bv.w;
    __half2* ph = (__half2*)(ah + (size_t)row * DMODEL);
    ph[t*2]   = __floats2half2_rn(o0, o1);
    ph[t*2+1] = __floats2half2_rn(o2, o3);
}

// ---------------- fp32 -> (hi, lo) fp16 split (weights), 8 elems/thread ----------------
__global__ __launch_bounds__(256) void split2(const float* __restrict__ src,
                                              __half* __restrict__ dh,
                                              __half* __restrict__ dl) {
    size_t i = ((size_t)blockIdx.x * 256 + threadIdx.x) * 8;
    const float4 f0 = *(const float4*)(src + i);
    const float4 f1 = *(const float4*)(src + i + 4);
    __half2 h0 = __floats2half2_rn(f0.x, f0.y);
    __half2 h1 = __floats2half2_rn(f0.z, f0.w);
    __half2 h2 = __floats2half2_rn(f1.x, f1.y);
    __half2 h3 = __floats2half2_rn(f1.z, f1.w);
    float2 g0 = __half22float2(h0), g1 = __half22float2(h1);
    float2 g2 = __half22float2(h2), g3 = __half22float2(h3);
    __half2 l0 = __floats2half2_rn(f0.x - g0.x, f0.y - g0.y);
    __half2 l1 = __floats2half2_rn(f0.z - g1.x, f0.w - g1.y);
    __half2 l2 = __floats2half2_rn(f1.x - g2.x, f1.y - g2.y);
    __half2 l3 = __floats2half2_rn(f1.z - g3.x, f1.w - g3.y);
    uint4 ph, pl;
    ph.x = *(uint32_t*)&h0; ph.y = *(uint32_t*)&h1;
    ph.z = *(uint32_t*)&h2; ph.w = *(uint32_t*)&h3;
    pl.x = *(uint32_t*)&l0; pl.y = *(uint32_t*)&l1;
    pl.z = *(uint32_t*)&l2; pl.w = *(uint32_t*)&l3;
    *(uint4*)(dh + i) = ph;
    *(uint4*)(dl + i) = pl;
}

__global__ void pack_bias(const float* __restrict__ a, const float* __restrict__ b,
                          const float* __restrict__ c, float* __restrict__ out) {
    int i = blockIdx.x * 256 + threadIdx.x;
    float v = (i < 1024) ? a[i] : (i < 2048) ? b[i - 1024] : c[i - 2048];
    out[i] = v;
}

// ---------------- PTX helpers ----------------
#define CP16(sa, ga) asm volatile("cp.async.cg.shared.global [%0], [%1], 16;\n" :: "r"(sa), "l"(ga))
#define COMMIT() asm volatile("cp.async.commit_group;\n" ::)
#define LDMX4(r0,r1,r2,r3,addr) asm volatile( \
    "ldmatrix.sync.aligned.m8n8.x4.shared.b16 {%0,%1,%2,%3}, [%4];" \
    : "=r"(r0), "=r"(r1), "=r"(r2), "=r"(r3) : "r"(addr))
#define LDMX4T(r0,r1,r2,r3,addr) asm volatile( \
    "ldmatrix.sync.aligned.m8n8.x4.trans.shared.b16 {%0,%1,%2,%3}, [%4];" \
    : "=r"(r0), "=r"(r1), "=r"(r2), "=r"(r3) : "r"(addr))
#define MMA16816(d, a0,a1,a2,a3, b0,b1) asm volatile( \
    "mma.sync.aligned.m16n8k16.row.col.f32.f16.f16.f32 " \
    "{%0,%1,%2,%3}, {%4,%5,%6,%7}, {%8,%9}, {%0,%1,%2,%3};" \
    : "+f"(d[0]), "+f"(d[1]), "+f"(d[2]), "+f"(d[3]) \
    : "r"(a0), "r"(a1), "r"(a2), "r"(a3), "r"(b0), "r"(b1))

// ---------------- compensated fp16 GEMM (2-term, BK=64, double buffer) ----------------
// C[M,N] = Ah[M,K] @ (Bh+Bl)[N,K]^T
// epi: 2 = bias+residual -> float C ; 3 = bias -> half Ch ; 4 = bias+GELU -> half Ch
#define GK      64                   // halves per k-tile
#define GSTRIDE 72                   // smem row stride (halves)
#define TILE_H  (128 * GSTRIDE)      // halves per 128xGK tile
#define STAGE_H (3 * TILE_H)         // Ah, Bh, Bl
#define GSMEM_BYTES (2 * STAGE_H * 2)   // 110592

__device__ __forceinline__ void g_load_stage(uint32_t smBase, int stg,
                                             const __half* gAh, const __half* gBh,
                                             const __half* gBl, int K, int k0, int tid) {
    const uint32_t sb = smBase + (uint32_t)(stg * STAGE_H * 2);
    #pragma unroll
    for (int i = 0; i < 4; i++) {
        const int idx = tid + i * 256;          // [0,1024)
        const int r = idx >> 3, sg = (idx & 7) * 8;
        const uint32_t so = (uint32_t)((r * GSTRIDE + sg) << 1);
        const size_t go = (size_t)r * K + k0 + sg;
        CP16(sb + so,                    gAh + go);
        CP16(sb + TILE_H * 2 + so,       gBh + go);
        CP16(sb + TILE_H * 4 + so,       gBl + go);
    }
    COMMIT();
}

__global__ __launch_bounds__(256, 2) void hgemm2t(const __half* __restrict__ Ah,
                                                  const __half* __restrict__ Bh,
                                                  const __half* __restrict__ Bl,
                                                  const float* __restrict__ bias,
                                                  const float* __restrict__ R,
                                                  float* __restrict__ C,
                                                  __half* __restrict__ Ch,
                                                  int M, int N, int K, int epi) {
    extern __shared__ __half sm16[];

    const int tid  = threadIdx.x;
    const int wid  = tid >> 5;
    const int lane = tid & 31;
    const int bm   = blockIdx.y * 128;
    const int bn   = blockIdx.x * 128;
    const int wm0  = (wid >> 2) * 64;
    const int wn0  = (wid & 3) * 32;

    float acc[4][4][4];
    #pragma unroll
    for (int i = 0; i < 4; i++)
        #pragma unroll
        for (int j = 0; j < 4; j++)
            #pragma unroll
            for (int t = 0; t < 4; t++) acc[i][j][t] = 0.f;

    const int nk = K >> 6;
    const uint32_t smBase = (uint32_t)__cvta_generic_to_shared(sm16);
    #define SADDR(stage, tile, row, col) (smBase + (((stage)*STAGE_H + (tile)*TILE_H + (row)*GSTRIDE + (col)) << 1))

    const __half* gAh = Ah + (size_t)bm * K;
    const __half* gBh = Bh + (size_t)bn * K;
    const __half* gBl = Bl + (size_t)bn * K;

    g_load_stage(smBase, 0, gAh, gBh, gBl, K, 0, tid);

    const int aRow  = (lane & 15);
    const int fBase = ((lane >> 4) << 3);

    for (int kt = 0; kt < nk; kt++) {
        const int buf = kt & 1;
        asm volatile("cp.async.wait_group 0;\n" ::);
        __syncthreads();
        if (kt + 1 < nk)
            g_load_stage(smBase, buf ^ 1, gAh, gBh, gBl, K, (kt + 1) << 6, tid);

        #pragma unroll
        for (int ks = 0; ks < 4; ks++) {
            const int fcol = ks * 16 + fBase;
            uint32_t bh[2][4], bl[2][4];
            #pragma unroll
            for (int nt2 = 0; nt2 < 2; nt2++) {
                LDMX4(bh[nt2][0], bh[nt2][1], bh[nt2][2], bh[nt2][3],
                      SADDR(buf, 1, wn0 + nt2 * 16 + aRow, fcol));
                LDMX4(bl[nt2][0], bl[nt2][1], bl[nt2][2], bl[nt2][3],
                      SADDR(buf, 2, wn0 + nt2 * 16 + aRow, fcol));
            }
            #pragma unroll
            for (int mt = 0; mt < 4; mt++) {
                uint32_t a0, a1, a2, a3;
                LDMX4(a0, a1, a2, a3, SADDR(buf, 0, wm0 + mt * 16 + aRow, fcol));
                #pragma unroll
                for (int nt = 0; nt < 4; nt++)
                    MMA16816(acc[mt][nt], a0, a1, a2, a3,
                             bh[nt >> 1][nt & 1], bh[nt >> 1][(nt & 1) + 2]);
                #pragma unroll
                for (int nt = 0; nt < 4; nt++)
                    MMA16816(acc[mt][nt], a0, a1, a2, a3,
                             bl[nt >> 1][nt & 1], bl[nt >> 1][(nt & 1) + 2]);
            }
        }
    }

    // ---- epilogue ----
    const int g  = lane >> 2;
    const int tg = lane & 3;
    #pragma unroll
    for (int mt = 0; mt < 4; mt++) {
        #pragma unroll
        for (int nt = 0; nt < 4; nt++) {
            const int col = bn + wn0 + nt * 8 + tg * 2;
            const float bx = bias[col], by = bias[col + 1];
            #pragma unroll
            for (int hh = 0; hh < 2; hh++) {
                const int row = bm + wm0 + mt * 16 + g + hh * 8;
                float v0 = acc[mt][nt][hh * 2 + 0] + bx;
                float v1 = acc[mt][nt][hh * 2 + 1] + by;
                if (epi == 4) {
                    v0 = 0.5f * v0 * (1.0f + erff(v0 * 0.7071067811865475f));
                    v1 = 0.5f * v1 * (1.0f + erff(v1 * 0.7071067811865475f));
                }
                if (epi == 2) {
                    const float2 rv = *(const float2*)&R[(size_t)row * N + col];
                    v0 += rv.x; v1 += rv.y;
                    float2 o; o.x = v0; o.y = v1;
                    *(float2*)&C[(size_t)row * N + col] = o;
                } else {
                    *(__half2*)&Ch[(size_t)row * N + col] = __floats2half2_rn(v0, v1);
                }
            }
        }
    }
}

// ---------------- tensor-core causal flash attention (q-tile 128, 8 warps) ----------------
#define QS 72
// dynamic smem halves: Q 128*72, K 2*64*72, V 2*64*72
#define ATTN_Q_OFF 0
#define ATTN_K_OFF (128 * QS)
#define ATTN_V_OFF (128 * QS + 2 * 64 * QS)
#define ATTN_SMEM_BYTES ((128 * QS + 4 * 64 * QS) * 2)

__global__ __launch_bounds__(256) void attn_tc(const __half* __restrict__ QKVh,
                                               __half* __restrict__ Oh) {
    extern __shared__ __half asm16[];

    const int bh = blockIdx.y;
    const int b  = bh >> 4;
    const int h  = bh & 15;
    const int q0 = blockIdx.x * 128;
    const int tid  = threadIdx.x;
    const int wq   = tid >> 5;
    const int lane = tid & 31;
    const int g  = lane >> 2;
    const int tg = lane & 3;

    const __half* Qg = QKVh + ((size_t)b * SEQ + q0) * QKVW + h * HDIM;
    const __half* Kg = QKVh + (size_t)b * SEQ * QKVW + DMODEL + h * HDIM;
    const __half* Vg = Kg + DMODEL;

    const uint32_t qB = (uint32_t)__cvta_generic_to_shared(asm16) + ATTN_Q_OFF * 2;
    const uint32_t kB = (uint32_t)__cvta_generic_to_shared(asm16) + ATTN_K_OFF * 2;
    const uint32_t vB = (uint32_t)__cvta_generic_to_shared(asm16) + ATTN_V_OFF * 2;
    const uint32_t bufStride = 64 * QS * 2;

    // Q: 128 rows x 8 chunks = 1024 ; K/V: 64 rows x 8 chunks = 512 each
    #pragma unroll
    for (int i = 0; i < 4; i++) {
        int idx = tid + i * 256;
        int r = idx >> 3, sg = (idx & 7) * 8;
        CP16(qB + (r * QS + sg) * 2, Qg + (size_t)r * QKVW + sg);
    }
    #pragma unroll
    for (int i = 0; i < 2; i++) {
        int idx = tid + i * 256;
        int r = idx >> 3, sg = (idx & 7) * 8;
        CP16(kB + (r * QS + sg) * 2, Kg + (size_t)r * QKVW + sg);
        CP16(vB + (r * QS + sg) * 2, Vg + (size_t)r * QKVW + sg);
    }
    COMMIT();

    uint32_t Qa[4][4];
    float    o[8][4];
    #pragma unroll
    for (int i = 0; i < 8; i++)
        #pragma unroll
        for (int j = 0; j < 4; j++) o[i][j] = 0.f;
    float m0 = -1e30f, m1 = -1e30f, l0 = 0.f, l1 = 0.f;

    const int nchunks = (q0 >> 6) + 2;
    for (int it = 0; it < nchunks; it++) {
        const int buf = it & 1;
        if (it + 1 < nchunks) {
            const int c1 = (it + 1) << 6;
            #pragma unroll
            for (int i = 0; i < 2; i++) {
                int idx = tid + i * 256;
                int r = idx >> 3, sg = (idx & 7) * 8;
                CP16(kB + (buf ^ 1) * bufStride + (r * QS + sg) * 2, Kg + (size_t)(c1 + r) * QKVW + sg);
                CP16(vB + (buf ^ 1) * bufStride + (r * QS + sg) * 2, Vg + (size_t)(c1 + r) * QKVW + sg);
            }
            COMMIT();
            asm volatile("cp.async.wait_group 1;\n" ::);
        } else {
            asm volatile("cp.async.wait_group 0;\n" ::);
        }
        __syncthreads();

        if (it == 0) {
            #pragma unroll
            for (int kk = 0; kk < 4; kk++) {
                uint32_t addr = qB + ((wq * 16 + (lane & 15)) * QS + kk * 16 + ((lane >> 4) << 3)) * 2;
                LDMX4(Qa[kk][0], Qa[kk][1], Qa[kk][2], Qa[kk][3], addr);
            }
        }

        float s[8][4];
        #pragma unroll
        for (int i = 0; i < 8; i++)
            #pragma unroll
            for (int j = 0; j < 4; j++) s[i][j] = 0.f;

        #pragma unroll
        for (int kk = 0; kk < 4; kk++) {
            #pragma unroll
            for (int nt2 = 0; nt2 < 4; nt2++) {
                uint32_t r0, r1, r2, r3;
                uint32_t addr = kB + buf * bufStride +
                    ((nt2 * 16 + (lane & 15)) * QS + kk * 16 + ((lane >> 4) << 3)) * 2;
                LDMX4(r0, r1, r2, r3, addr);
                MMA16816(s[nt2 * 2],     Qa[kk][0], Qa[kk][1], Qa[kk][2], Qa[kk][3], r0, r2);
                MMA16816(s[nt2 * 2 + 1], Qa[kk][0], Qa[kk][1], Qa[kk][2], Qa[kk][3], r1, r3);
            }
        }

        #pragma unroll
        for (int nt = 0; nt < 8; nt++)
            #pragma unroll
            for (int j = 0; j < 4; j++) s[nt][j] *= 0.125f;

        if (it >= nchunks - 2) {   // chunks overlapping the diagonal band
            const int c0 = it << 6;
            const int row0a = q0 + wq * 16 + g;
            const int row1a = row0a + 8;
            #pragma unroll
            for (int nt = 0; nt < 8; nt++) {
                const int key = c0 + nt * 8 + 2 * tg;
                if (key     > row0a) s[nt][0] = -1e30f;
                if (key + 1 > row0a) s[nt][1] = -1e30f;
                if (key     > row1a) s[nt][2] = -1e30f;
                if (key + 1 > row1a) s[nt][3] = -1e30f;
            }
        }

        float mx0 = -1e30f, mx1 = -1e30f;
        #pragma unroll
        for (int nt = 0; nt < 8; nt++) {
            mx0 = fmaxf(mx0, fmaxf(s[nt][0], s[nt][1]));
            mx1 = fmaxf(mx1, fmaxf(s[nt][2], s[nt][3]));
        }
        mx0 = fmaxf(mx0, __shfl_xor_sync(0xffffffffu, mx0, 1));
        mx0 = fmaxf(mx0, __shfl_xor_sync(0xffffffffu, mx0, 2));
        mx1 = fmaxf(mx1, __shfl_xor_sync(0xffffffffu, mx1, 1));
        mx1 = fmaxf(mx1, __shfl_xor_sync(0xffffffffu, mx1, 2));
        const float mn0 = fmaxf(m0, mx0), mn1 = fmaxf(m1, mx1);
        const float cr0 = __expf(m0 - mn0), cr1 = __expf(m1 - mn1);
        float ps0 = 0.f, ps1 = 0.f;
        #pragma unroll
        for (int nt = 0; nt < 8; nt++) {
            s[nt][0] = __expf(s[nt][0] - mn0);
            s[nt][1] = __expf(s[nt][1] - mn0);
            s[nt][2] = __expf(s[nt][2] - mn1);
            s[nt][3] = __expf(s[nt][3] - mn1);
            ps0 += s[nt][0] + s[nt][1];
            ps1 += s[nt][2] + s[nt][3];
        }
        ps0 += __shfl_xor_sync(0xffffffffu, ps0, 1);
        ps0 += __shfl_xor_sync(0xffffffffu, ps0, 2);
        ps1 += __shfl_xor_sync(0xffffffffu, ps1, 1);
        ps1 += __shfl_xor_sync(0xffffffffu, ps1, 2);
        l0 = l0 * cr0 + ps0;
        l1 = l1 * cr1 + ps1;
        m0 = mn0; m1 = mn1;
        #pragma unroll
        for (int nd = 0; nd < 8; nd++) {
            o[nd][0] *= cr0; o[nd][1] *= cr0;
            o[nd][2] *= cr1; o[nd][3] *= cr1;
        }

        #pragma unroll
        for (int kk = 0; kk < 4; kk++) {
            __half2 t0 = __floats2half2_rn(s[2*kk][0],   s[2*kk][1]);
            __half2 t1 = __floats2half2_rn(s[2*kk][2],   s[2*kk][3]);
            __half2 t2 = __floats2half2_rn(s[2*kk+1][0], s[2*kk+1][1]);
            __half2 t3 = __floats2half2_rn(s[2*kk+1][2], s[2*kk+1][3]);
            uint32_t pa0 = *(uint32_t*)&t0, pa1 = *(uint32_t*)&t1;
            uint32_t pa2 = *(uint32_t*)&t2, pa3 = *(uint32_t*)&t3;
            #pragma unroll
            for (int nd2 = 0; nd2 < 4; nd2++) {
                uint32_t r0, r1, r2, r3;
                uint32_t addr = vB + buf * bufStride +
                    ((kk * 16 + (lane & 15)) * QS + nd2 * 16 + ((lane >> 4) << 3)) * 2;
                LDMX4T(r0, r1, r2, r3, addr);
                MMA16816(o[nd2 * 2],     pa0, pa1, pa2, pa3, r0, r1);
                MMA16816(o[nd2 * 2 + 1], pa0, pa1, pa2, pa3, r2, r3);
            }
        }
        __syncthreads();
    }

    const float inv0 = 1.f / l0, inv1 = 1.f / l1;
    const int row0 = q0 + wq * 16 + g;
    const size_t ob0 = ((size_t)b * SEQ + row0) * DMODEL + h * HDIM;
    const size_t ob1 = ob0 + 8 * DMODEL;
    #pragma unroll
    for (int nd = 0; nd < 8; nd++) {
        const int d = nd * 8 + 2 * tg;
        *(__half2*)&Oh[ob0 + d] = __floats2half2_rn(o[nd][0] * inv0, o[nd][1] * inv0);
        *(__half2*)&Oh[ob1 + d] = __floats2half2_rn(o[nd][2] * inv1, o[nd][3] * inv1);
    }
}

// ---------------- launcher ----------------
extern "C" void kernel_launch(void* const* d_in, const int* in_sizes, int n_in,
                              void* d_out, int out_size) {
    const float* x     = (const float*)d_in[0];
    const float* Wq    = (const float*)d_in[2];
    const float* bq    = (const float*)d_in[3];
    const float* Wk    = (const float*)d_in[4];
    const float* bk    = (const float*)d_in[5];
    const float* Wv    = (const float*)d_in[6];
    const float* bv    = (const float*)d_in[7];
    const float* Wo    = (const float*)d_in[8];
    const float* bo    = (const float*)d_in[9];
    const float* W1    = (const float*)d_in[10];
    const float* b1    = (const float*)d_in[11];
    const float* W2    = (const float*)d_in[12];
    const float* b2    = (const float*)d_in[13];
    const float* g1    = (const float*)d_in[14];
    const float* beta1 = (const float*)d_in[15];
    const float* g2    = (const float*)d_in[16];
    const float* beta2 = (const float*)d_in[17];
    float* out = (float*)d_out;

    float *x2, *bqkv;
    __half *qkvh, *ah, *hh, *wh, *wl;
    cudaGetSymbolAddress((void**)&x2,   g_x2);
    cudaGetSymbolAddress((void**)&bqkv, g_bqkv);
    cudaGetSymbolAddress((void**)&qkvh, g_qkvh);
    cudaGetSymbolAddress((void**)&ah,   g_ah);
    cudaGetSymbolAddress((void**)&hh,   g_hh);
    cudaGetSymbolAddress((void**)&wh,   g_wh);
    cudaGetSymbolAddress((void**)&wl,   g_wl);

    static bool attr_set = false;
    if (!attr_set) {
        cudaFuncSetAttribute(hgemm2t, cudaFuncAttributeMaxDynamicSharedMemorySize, GSMEM_BYTES);
        cudaFuncSetAttribute(attn_tc, cudaFuncAttributeMaxDynamicSharedMemorySize, ATTN_SMEM_BYTES);
        attr_set = true;
    }

    const int M = MROWS, D = DMODEL, F = FFDIM;
    const size_t DD = (size_t)D * D;

    // LN1 -> fp16
    ln_h16<<<M, 256>>>(x, g1, beta1, ah);

    // fused QKV GEMM -> fp16 output (N = 3072)
    split2<<<(int)(DD / 8) / 256, 256>>>(Wq, wh, wl);
    split2<<<(int)(DD / 8) / 256, 256>>>(Wk, wh + DD, wl + DD);
    split2<<<(int)(DD / 8) / 256, 256>>>(Wv, wh + 2 * DD, wl + 2 * DD);
    pack_bias<<<QKVW / 256, 256>>>(bq, bk, bv, bqkv);
    dim3 gQKV(QKVW / 128, M / 128);
    hgemm2t<<<gQKV, 256, GSMEM_BYTES>>>(ah, wh, wl, bqkv, nullptr,
                                        nullptr, qkvh, M, QKVW, D, 3);

    // tensor-core causal attention -> ctx fp16
    dim3 gA(SEQ / 128, BSZ * NHEADS);
    attn_tc<<<gA, 256, ATTN_SMEM_BYTES>>>(qkvh, ah);

    // output projection + residual -> x2 (fp32)
    split2<<<(int)(DD / 8) / 256, 256>>>(Wo, wh, wl);
    dim3 gD(D / 128, M / 128);
    hgemm2t<<<gD, 256, GSMEM_BYTES>>>(ah, wh, wl, bo, x,
                                      x2, nullptr, M, D, D, 2);

    // LN2 -> fp16
    ln_h16<<<M, 256>>>(x2, g2, beta2, ah);

    // FFN1 (GELU) -> hidden fp16 (N = 4096)
    split2<<<(int)((size_t)F * D / 8) / 256, 256>>>(W1, wh, wl);
    dim3 gF1(F / 128, M / 128);
    hgemm2t<<<gF1, 256, GSMEM_BYTES>>>(ah, wh, wl, b1, nullptr,
                                       nullptr, hh, M, F, D, 4);

    // FFN2 + residual -> out (fp32), K = 4096
    split2<<<(int)((size_t)D * F / 8) / 256, 256>>>(W2, wh, wl);
    hgemm2t<<<gD, 256, GSMEM_BYTES>>>(hh, wh, wl, b2, x2,
                                      out, nullptr, M, D, F, 2);
}

// round 8
// speedup vs baseline: 6.5027x; 1.5644x over previous
#include <cuda_runtime.h>
#include <cuda_fp16.h>
#include <math.h>
#include <stdint.h>

// ---------------- problem constants ----------------
#define BSZ    2
#define SEQ    2048
#define DMODEL 1024
#define NHEADS 16
#define HDIM   64
#define FFDIM  4096
#define MROWS (BSZ*SEQ)          // 4096
#define QKVW  (3*DMODEL)         // 3072
#define LN_EPS 1e-5f

// ---------------- scratch (device globals; no allocs) ----------------
__device__ float  g_x2  [MROWS*DMODEL];
__device__ float  g_bqkv[QKVW];
__device__ __half g_qkvh[(size_t)MROWS*QKVW];
__device__ __half g_ah[(size_t)MROWS*DMODEL];    // activations (fp16)
__device__ __half g_hh[(size_t)MROWS*FFDIM];     // FFN hidden (fp16)
__device__ __half g_wh[(size_t)FFDIM*DMODEL];    // weights (fp16)

// ---------------- LayerNorm -> fp16 directly ----------------
__global__ __launch_bounds__(256) void ln_h16(const float* __restrict__ x,
                                              const float* __restrict__ g,
                                              const float* __restrict__ b,
                                              __half* __restrict__ ah) {
    int row = blockIdx.x;
    int t   = threadIdx.x;
    const float4 v = ((const float4*)(x + (size_t)row * DMODEL))[t];
    float s  = v.x + v.y + v.z + v.w;
    float ss = v.x*v.x + v.y*v.y + v.z*v.z + v.w*v.w;
    #pragma unroll
    for (int o = 16; o; o >>= 1) {
        s  += __shfl_xor_sync(0xffffffffu, s,  o);
        ss += __shfl_xor_sync(0xffffffffu, ss, o);
    }
    __shared__ float rs[8], rss[8];
    if ((t & 31) == 0) { rs[t >> 5] = s; rss[t >> 5] = ss; }
    __syncthreads();
    float S = 0.f, SS = 0.f;
    #pragma unroll
    for (int i = 0; i < 8; i++) { S += rs[i]; SS += rss[i]; }
    float mean = S * (1.f / DMODEL);
    float var  = SS * (1.f / DMODEL) - mean * mean;
    float rstd = rsqrtf(var + LN_EPS);
    const float4 gv = ((const float4*)g)[t];
    const float4 bv = ((const float4*)b)[t];
    float o0 = (v.x - mean) * rstd * gv.x + bv.x;
    float o1 = (v.y - mean) * rstd * gv.y + bv.y;
    float o2 = (v.z - mean) * rstd * gv.z + bv.z;
    float o3 = (v.w - mean) * rstd * gv.w + bv.w;
    __half2* ph = (__half2*)(ah + (size_t)row * DMODEL);
    ph[t*2]   = __floats2half2_rn(o0, o1);
    ph[t*2+1] = __floats2half2_rn(o2, o3);
}

// ---------------- fp32 -> fp16 convert (weights), 8 elems/thread ----------------
__global__ __launch_bounds__(256) void cvt16(const float* __restrict__ src,
                                             __half* __restrict__ dst) {
    size_t i = ((size_t)blockIdx.x * 256 + threadIdx.x) * 8;
    const float4 f0 = *(const float4*)(src + i);
    const float4 f1 = *(const float4*)(src + i + 4);
    __half2 h0 = __floats2half2_rn(f0.x, f0.y);
    __half2 h1 = __floats2half2_rn(f0.z, f0.w);
    __half2 h2 = __floats2half2_rn(f1.x, f1.y);
    __half2 h3 = __floats2half2_rn(f1.z, f1.w);
    uint4 ph;
    ph.x = *(uint32_t*)&h0; ph.y = *(uint32_t*)&h1;
    ph.z = *(uint32_t*)&h2; ph.w = *(uint32_t*)&h3;
    *(uint4*)(dst + i) = ph;
}

__global__ void pack_bias(const float* __restrict__ a, const float* __restrict__ b,
                          const float* __restrict__ c, float* __restrict__ out) {
    int i = blockIdx.x * 256 + threadIdx.x;
    float v = (i < 1024) ? a[i] : (i < 2048) ? b[i - 1024] : c[i - 2048];
    out[i] = v;
}

// ---------------- PTX helpers ----------------
#define CP16(sa, ga) asm volatile("cp.async.cg.shared.global [%0], [%1], 16;\n" :: "r"(sa), "l"(ga))
#define COMMIT() asm volatile("cp.async.commit_group;\n" ::)
#define LDMX4(r0,r1,r2,r3,addr) asm volatile( \
    "ldmatrix.sync.aligned.m8n8.x4.shared.b16 {%0,%1,%2,%3}, [%4];" \
    : "=r"(r0), "=r"(r1), "=r"(r2), "=r"(r3) : "r"(addr))
#define LDMX4T(r0,r1,r2,r3,addr) asm volatile( \
    "ldmatrix.sync.aligned.m8n8.x4.trans.shared.b16 {%0,%1,%2,%3}, [%4];" \
    : "=r"(r0), "=r"(r1), "=r"(r2), "=r"(r3) : "r"(addr))
#define MMA16816(d, a0,a1,a2,a3, b0,b1) asm volatile( \
    "mma.sync.aligned.m16n8k16.row.col.f32.f16.f16.f32 " \
    "{%0,%1,%2,%3}, {%4,%5,%6,%7}, {%8,%9}, {%0,%1,%2,%3};" \
    : "+f"(d[0]), "+f"(d[1]), "+f"(d[2]), "+f"(d[3]) \
    : "r"(a0), "r"(a1), "r"(a2), "r"(a3), "r"(b0), "r"(b1))

// ---------------- single-term fp16 GEMM (BK=64, double buffer) ----------------
// C[M,N] = A[M,K] @ B[N,K]^T  (fp16 inputs, fp32 accumulate)
// epi: 2 = bias+residual -> float C ; 3 = bias -> half Ch ; 4 = bias+GELU -> half Ch
#define GSTRIDE 72                   // smem row stride (halves)
#define TILE_H  (128 * GSTRIDE)      // halves per 128x64 tile
#define STAGE_H (2 * TILE_H)         // A, B
#define GSMEM_BYTES (2 * STAGE_H * 2)   // 73728

__device__ __forceinline__ void g_load_stage(uint32_t smBase, int stg,
                                             const __half* gA, const __half* gB,
                                             int K, int k0, int tid) {
    const uint32_t sb = smBase + (uint32_t)(stg * STAGE_H * 2);
    #pragma unroll
    for (int i = 0; i < 4; i++) {
        const int idx = tid + i * 256;          // [0,1024)
        const int r = idx >> 3, sg = (idx & 7) * 8;
        const uint32_t so = (uint32_t)((r * GSTRIDE + sg) << 1);
        const size_t go = (size_t)r * K + k0 + sg;
        CP16(sb + so,              gA + go);
        CP16(sb + TILE_H * 2 + so, gB + go);
    }
    COMMIT();
}

__global__ __launch_bounds__(256, 2) void hgemm1t(const __half* __restrict__ A,
                                                  const __half* __restrict__ B,
                                                  const float* __restrict__ bias,
                                                  const float* __restrict__ R,
                                                  float* __restrict__ C,
                                                  __half* __restrict__ Ch,
                                                  int M, int N, int K, int epi) {
    extern __shared__ __half sm16[];

    const int tid  = threadIdx.x;
    const int wid  = tid >> 5;
    const int lane = tid & 31;
    const int bm   = blockIdx.y * 128;
    const int bn   = blockIdx.x * 128;
    const int wm0  = (wid >> 2) * 64;
    const int wn0  = (wid & 3) * 32;

    float acc[4][4][4];
    #pragma unroll
    for (int i = 0; i < 4; i++)
        #pragma unroll
        for (int j = 0; j < 4; j++)
            #pragma unroll
            for (int t = 0; t < 4; t++) acc[i][j][t] = 0.f;

    const int nk = K >> 6;
    const uint32_t smBase = (uint32_t)__cvta_generic_to_shared(sm16);
    #define SADDR(stage, tile, row, col) (smBase + (((stage)*STAGE_H + (tile)*TILE_H + (row)*GSTRIDE + (col)) << 1))

    const __half* gA = A + (size_t)bm * K;
    const __half* gB = B + (size_t)bn * K;

    g_load_stage(smBase, 0, gA, gB, K, 0, tid);

    const int aRow  = (lane & 15);
    const int fBase = ((lane >> 4) << 3);

    for (int kt = 0; kt < nk; kt++) {
        const int buf = kt & 1;
        asm volatile("cp.async.wait_group 0;\n" ::);
        __syncthreads();
        if (kt + 1 < nk)
            g_load_stage(smBase, buf ^ 1, gA, gB, K, (kt + 1) << 6, tid);

        #pragma unroll
        for (int ks = 0; ks < 4; ks++) {
            const int fcol = ks * 16 + fBase;
            uint32_t bh[2][4];
            #pragma unroll
            for (int nt2 = 0; nt2 < 2; nt2++) {
                LDMX4(bh[nt2][0], bh[nt2][1], bh[nt2][2], bh[nt2][3],
                      SADDR(buf, 1, wn0 + nt2 * 16 + aRow, fcol));
            }
            #pragma unroll
            for (int mt = 0; mt < 4; mt++) {
                uint32_t a0, a1, a2, a3;
                LDMX4(a0, a1, a2, a3, SADDR(buf, 0, wm0 + mt * 16 + aRow, fcol));
                #pragma unroll
                for (int nt = 0; nt < 4; nt++)
                    MMA16816(acc[mt][nt], a0, a1, a2, a3,
                             bh[nt >> 1][nt & 1], bh[nt >> 1][(nt & 1) + 2]);
            }
        }
    }

    // ---- epilogue ----
    const int g  = lane >> 2;
    const int tg = lane & 3;
    #pragma unroll
    for (int mt = 0; mt < 4; mt++) {
        #pragma unroll
        for (int nt = 0; nt < 4; nt++) {
            const int col = bn + wn0 + nt * 8 + tg * 2;
            const float bx = bias[col], by = bias[col + 1];
            #pragma unroll
            for (int hh = 0; hh < 2; hh++) {
                const int row = bm + wm0 + mt * 16 + g + hh * 8;
                float v0 = acc[mt][nt][hh * 2 + 0] + bx;
                float v1 = acc[mt][nt][hh * 2 + 1] + by;
                if (epi == 4) {
                    v0 = 0.5f * v0 * (1.0f + erff(v0 * 0.7071067811865475f));
                    v1 = 0.5f * v1 * (1.0f + erff(v1 * 0.7071067811865475f));
                }
                if (epi == 2) {
                    const float2 rv = *(const float2*)&R[(size_t)row * N + col];
                    v0 += rv.x; v1 += rv.y;
                    float2 o; o.x = v0; o.y = v1;
                    *(float2*)&C[(size_t)row * N + col] = o;
                } else {
                    *(__half2*)&Ch[(size_t)row * N + col] = __floats2half2_rn(v0, v1);
                }
            }
        }
    }
}

// ---------------- tensor-core causal flash attention (q-tile 128, 8 warps) ----------------
#define QS 72
#define ATTN_Q_OFF 0
#define ATTN_K_OFF (128 * QS)
#define ATTN_V_OFF (128 * QS + 2 * 64 * QS)
#define ATTN_SMEM_BYTES ((128 * QS + 4 * 64 * QS) * 2)

__global__ __launch_bounds__(256) void attn_tc(const __half* __restrict__ QKVh,
                                               __half* __restrict__ Oh) {
    extern __shared__ __half asm16[];

    const int bh = blockIdx.y;
    const int b  = bh >> 4;
    const int h  = bh & 15;
    const int q0 = blockIdx.x * 128;
    const int tid  = threadIdx.x;
    const int wq   = tid >> 5;
    const int lane = tid & 31;
    const int g  = lane >> 2;
    const int tg = lane & 3;

    const __half* Qg = QKVh + ((size_t)b * SEQ + q0) * QKVW + h * HDIM;
    const __half* Kg = QKVh + (size_t)b * SEQ * QKVW + DMODEL + h * HDIM;
    const __half* Vg = Kg + DMODEL;

    const uint32_t qB = (uint32_t)__cvta_generic_to_shared(asm16) + ATTN_Q_OFF * 2;
    const uint32_t kB = (uint32_t)__cvta_generic_to_shared(asm16) + ATTN_K_OFF * 2;
    const uint32_t vB = (uint32_t)__cvta_generic_to_shared(asm16) + ATTN_V_OFF * 2;
    const uint32_t bufStride = 64 * QS * 2;

    #pragma unroll
    for (int i = 0; i < 4; i++) {
        int idx = tid + i * 256;
        int r = idx >> 3, sg = (idx & 7) * 8;
        CP16(qB + (r * QS + sg) * 2, Qg + (size_t)r * QKVW + sg);
    }
    #pragma unroll
    for (int i = 0; i < 2; i++) {
        int idx = tid + i * 256;
        int r = idx >> 3, sg = (idx & 7) * 8;
        CP16(kB + (r * QS + sg) * 2, Kg + (size_t)r * QKVW + sg);
        CP16(vB + (r * QS + sg) * 2, Vg + (size_t)r * QKVW + sg);
    }
    COMMIT();

    uint32_t Qa[4][4];
    float    o[8][4];
    #pragma unroll
    for (int i = 0; i < 8; i++)
        #pragma unroll
        for (int j = 0; j < 4; j++) o[i][j] = 0.f;
    float m0 = -1e30f, m1 = -1e30f, l0 = 0.f, l1 = 0.f;

    const int nchunks = (q0 >> 6) + 2;
    for (int it = 0; it < nchunks; it++) {
        const int buf = it & 1;
        if (it + 1 < nchunks) {
            const int c1 = (it + 1) << 6;
            #pragma unroll
            for (int i = 0; i < 2; i++) {
                int idx = tid + i * 256;
                int r = idx >> 3, sg = (idx & 7) * 8;
                CP16(kB + (buf ^ 1) * bufStride + (r * QS + sg) * 2, Kg + (size_t)(c1 + r) * QKVW + sg);
                CP16(vB + (buf ^ 1) * bufStride + (r * QS + sg) * 2, Vg + (size_t)(c1 + r) * QKVW + sg);
            }
            COMMIT();
            asm volatile("cp.async.wait_group 1;\n" ::);
        } else {
            asm volatile("cp.async.wait_group 0;\n" ::);
        }
        __syncthreads();

        if (it == 0) {
            #pragma unroll
            for (int kk = 0; kk < 4; kk++) {
                uint32_t addr = qB + ((wq * 16 + (lane & 15)) * QS + kk * 16 + ((lane >> 4) << 3)) * 2;
                LDMX4(Qa[kk][0], Qa[kk][1], Qa[kk][2], Qa[kk][3], addr);
            }
        }

        float s[8][4];
        #pragma unroll
        for (int i = 0; i < 8; i++)
            #pragma unroll
            for (int j = 0; j < 4; j++) s[i][j] = 0.f;

        #pragma unroll
        for (int kk = 0; kk < 4; kk++) {
            #pragma unroll
            for (int nt2 = 0; nt2 < 4; nt2++) {
                uint32_t r0, r1, r2, r3;
                uint32_t addr = kB + buf * bufStride +
                    ((nt2 * 16 + (lane & 15)) * QS + kk * 16 + ((lane >> 4) << 3)) * 2;
                LDMX4(r0, r1, r2, r3, addr);
                MMA16816(s[nt2 * 2],     Qa[kk][0], Qa[kk][1], Qa[kk][2], Qa[kk][3], r0, r2);
                MMA16816(s[nt2 * 2 + 1], Qa[kk][0], Qa[kk][1], Qa[kk][2], Qa[kk][3], r1, r3);
            }
        }

        #pragma unroll
        for (int nt = 0; nt < 8; nt++)
            #pragma unroll
            for (int j = 0; j < 4; j++) s[nt][j] *= 0.125f;

        if (it >= nchunks - 2) {
            const int c0 = it << 6;
            const int row0a = q0 + wq * 16 + g;
            const int row1a = row0a + 8;
            #pragma unroll
            for (int nt = 0; nt < 8; nt++) {
                const int key = c0 + nt * 8 + 2 * tg;
                if (key     > row0a) s[nt][0] = -1e30f;
                if (key + 1 > row0a) s[nt][1] = -1e30f;
                if (key     > row1a) s[nt][2] = -1e30f;
                if (key + 1 > row1a) s[nt][3] = -1e30f;
            }
        }

        float mx0 = -1e30f, mx1 = -1e30f;
        #pragma unroll
        for (int nt = 0; nt < 8; nt++) {
            mx0 = fmaxf(mx0, fmaxf(s[nt][0], s[nt][1]));
            mx1 = fmaxf(mx1, fmaxf(s[nt][2], s[nt][3]));
        }
        mx0 = fmaxf(mx0, __shfl_xor_sync(0xffffffffu, mx0, 1));
        mx0 = fmaxf(mx0, __shfl_xor_sync(0xffffffffu, mx0, 2));
        mx1 = fmaxf(mx1, __shfl_xor_sync(0xffffffffu, mx1, 1));
        mx1 = fmaxf(mx1, __shfl_xor_sync(0xffffffffu, mx1, 2));
        const float mn0 = fmaxf(m0, mx0), mn1 = fmaxf(m1, mx1);
        const float cr0 = __expf(m0 - mn0), cr1 = __expf(m1 - mn1);
        float ps0 = 0.f, ps1 = 0.f;
        #pragma unroll
        for (int nt = 0; nt < 8; nt++) {
            s[nt][0] = __expf(s[nt][0] - mn0);
            s[nt][1] = __expf(s[nt][1] - mn0);
            s[nt][2] = __expf(s[nt][2] - mn1);
            s[nt][3] = __expf(s[nt][3] - mn1);
            ps0 += s[nt][0] + s[nt][1];
            ps1 += s[nt][2] + s[nt][3];
        }
        ps0 += __shfl_xor_sync(0xffffffffu, ps0, 1);
        ps0 += __shfl_xor_sync(0xffffffffu, ps0, 2);
        ps1 += __shfl_xor_sync(0xffffffffu, ps1, 1);
        ps1 += __shfl_xor_sync(0xffffffffu, ps1, 2);
        l0 = l0 * cr0 + ps0;
        l1 = l1 * cr1 + ps1;
        m0 = mn0; m1 = mn1;
        #pragma unroll
        for (int nd = 0; nd < 8; nd++) {
            o[nd][0] *= cr0; o[nd][1] *= cr0;
            o[nd][2] *= cr1; o[nd][3] *= cr1;
        }

        #pragma unroll
        for (int kk = 0; kk < 4; kk++) {
            __half2 t0 = __floats2half2_rn(s[2*kk][0],   s[2*kk][1]);
            __half2 t1 = __floats2half2_rn(s[2*kk][2],   s[2*kk][3]);
            __half2 t2 = __floats2half2_rn(s[2*kk+1][0], s[2*kk+1][1]);
            __half2 t3 = __floats2half2_rn(s[2*kk+1][2], s[2*kk+1][3]);
            uint32_t pa0 = *(uint32_t*)&t0, pa1 = *(uint32_t*)&t1;
            uint32_t pa2 = *(uint32_t*)&t2, pa3 = *(uint32_t*)&t3;
            #pragma unroll
            for (int nd2 = 0; nd2 < 4; nd2++) {
                uint32_t r0, r1, r2, r3;
                uint32_t addr = vB + buf * bufStride +
                    ((kk * 16 + (lane & 15)) * QS + nd2 * 16 + ((lane >> 4) << 3)) * 2;
                LDMX4T(r0, r1, r2, r3, addr);
                MMA16816(o[nd2 * 2],     pa0, pa1, pa2, pa3, r0, r1);
                MMA16816(o[nd2 * 2 + 1], pa0, pa1, pa2, pa3, r2, r3);
            }
        }
        __syncthreads();
    }

    const float inv0 = 1.f / l0, inv1 = 1.f / l1;
    const int row0 = q0 + wq * 16 + g;
    const size_t ob0 = ((size_t)b * SEQ + row0) * DMODEL + h * HDIM;
    const size_t ob1 = ob0 + 8 * DMODEL;
    #pragma unroll
    for (int nd = 0; nd < 8; nd++) {
        const int d = nd * 8 + 2 * tg;
        *(__half2*)&Oh[ob0 + d] = __floats2half2_rn(o[nd][0] * inv0, o[nd][1] * inv0);
        *(__half2*)&Oh[ob1 + d] = __floats2half2_rn(o[nd][2] * inv1, o[nd][3] * inv1);
    }
}

// ---------------- launcher ----------------
extern "C" void kernel_launch(void* const* d_in, const int* in_sizes, int n_in,
                              void* d_out, int out_size) {
    const float* x     = (const float*)d_in[0];
    const float* Wq    = (const float*)d_in[2];
    const float* bq    = (const float*)d_in[3];
    const float* Wk    = (const float*)d_in[4];
    const float* bk    = (const float*)d_in[5];
    const float* Wv    = (const float*)d_in[6];
    const float* bv    = (const float*)d_in[7];
    const float* Wo    = (const float*)d_in[8];
    const float* bo    = (const float*)d_in[9];
    const float* W1    = (const float*)d_in[10];
    const float* b1    = (const float*)d_in[11];
    const float* W2    = (const float*)d_in[12];
    const float* b2    = (const float*)d_in[13];
    const float* g1    = (const float*)d_in[14];
    const float* beta1 = (const float*)d_in[15];
    const float* g2    = (const float*)d_in[16];
    const float* beta2 = (const float*)d_in[17];
    float* out = (float*)d_out;

    float *x2, *bqkv;
    __half *qkvh, *ah, *hh, *wh;
    cudaGetSymbolAddress((void**)&x2,   g_x2);
    cudaGetSymbolAddress((void**)&bqkv, g_bqkv);
    cudaGetSymbolAddress((void**)&qkvh, g_qkvh);
    cudaGetSymbolAddress((void**)&ah,   g_ah);
    cudaGetSymbolAddress((void**)&hh,   g_hh);
    cudaGetSymbolAddress((void**)&wh,   g_wh);

    static bool attr_set = false;
    if (!attr_set) {
        cudaFuncSetAttribute(hgemm1t, cudaFuncAttributeMaxDynamicSharedMemorySize, GSMEM_BYTES);
        cudaFuncSetAttribute(attn_tc, cudaFuncAttributeMaxDynamicSharedMemorySize, ATTN_SMEM_BYTES);
        attr_set = true;
    }

    const int M = MROWS, D = DMODEL, F = FFDIM;
    const size_t DD = (size_t)D * D;

    // LN1 -> fp16
    ln_h16<<<M, 256>>>(x, g1, beta1, ah);

    // fused QKV GEMM -> fp16 output (N = 3072)
    cvt16<<<(int)(DD / 8) / 256, 256>>>(Wq, wh);
    cvt16<<<(int)(DD / 8) / 256, 256>>>(Wk, wh + DD);
    cvt16<<<(int)(DD / 8) / 256, 256>>>(Wv, wh + 2 * DD);
    pack_bias<<<QKVW / 256, 256>>>(bq, bk, bv, bqkv);
    dim3 gQKV(QKVW / 128, M / 128);
    hgemm1t<<<gQKV, 256, GSMEM_BYTES>>>(ah, wh, bqkv, nullptr,
                                        nullptr, qkvh, M, QKVW, D, 3);

    // tensor-core causal attention -> ctx fp16
    dim3 gA(SEQ / 128, BSZ * NHEADS);
    attn_tc<<<gA, 256, ATTN_SMEM_BYTES>>>(qkvh, ah);

    // output projection + residual -> x2 (fp32)
    cvt16<<<(int)(DD / 8) / 256, 256>>>(Wo, wh);
    dim3 gD(D / 128, M / 128);
    hgemm1t<<<gD, 256, GSMEM_BYTES>>>(ah, wh, bo, x,
                                      x2, nullptr, M, D, D, 2);

    // LN2 -> fp16
    ln_h16<<<M, 256>>>(x2, g2, beta2, ah);

    // FFN1 (GELU) -> hidden fp16 (N = 4096)
    cvt16<<<(int)((size_t)F * D / 8) / 256, 256>>>(W1, wh);
    dim3 gF1(F / 128, M / 128);
    hgemm1t<<<gF1, 256, GSMEM_BYTES>>>(ah, wh, b1, nullptr,
                                       nullptr, hh, M, F, D, 4);

    // FFN2 + residual -> out (fp32), K = 4096
    cvt16<<<(int)((size_t)D * F / 8) / 256, 256>>>(W2, wh);
    hgemm1t<<<gD, 256, GSMEM_BYTES>>>(hh, wh, b2, x2,
                                      out, nullptr, M, D, F, 2);
}

// round 9
// speedup vs baseline: 6.6473x; 1.0222x over previous
#include <cuda_runtime.h>
#include <cuda_fp16.h>
#include <math.h>
#include <stdint.h>

// ---------------- problem constants ----------------
#define BSZ    2
#define SEQ    2048
#define DMODEL 1024
#define NHEADS 16
#define HDIM   64
#define FFDIM  4096
#define MROWS (BSZ*SEQ)          // 4096
#define QKVW  (3*DMODEL)         // 3072
#define LN_EPS 1e-5f

// ---------------- scratch (device globals; no allocs) ----------------
__device__ float  g_x2  [MROWS*DMODEL];
__device__ float  g_bqkv[QKVW];
__device__ __half g_qkvh[(size_t)MROWS*QKVW];
__device__ __half g_ah[(size_t)MROWS*DMODEL];        // activations (fp16)
__device__ __half g_hh[(size_t)MROWS*FFDIM];         // FFN hidden (fp16)
__device__ __half g_wh[(size_t)12*1024*1024];        // all weights fp16 (24MB)

// ---------------- LayerNorm -> fp16 directly ----------------
__global__ __launch_bounds__(256) void ln_h16(const float* __restrict__ x,
                                              const float* __restrict__ g,
                                              const float* __restrict__ b,
                                              __half* __restrict__ ah) {
    int row = blockIdx.x;
    int t   = threadIdx.x;
    const float4 v = ((const float4*)(x + (size_t)row * DMODEL))[t];
    float s  = v.x + v.y + v.z + v.w;
    float ss = v.x*v.x + v.y*v.y + v.z*v.z + v.w*v.w;
    #pragma unroll
    for (int o = 16; o; o >>= 1) {
        s  += __shfl_xor_sync(0xffffffffu, s,  o);
        ss += __shfl_xor_sync(0xffffffffu, ss, o);
    }
    __shared__ float rs[8], rss[8];
    if ((t & 31) == 0) { rs[t >> 5] = s; rss[t >> 5] = ss; }
    __syncthreads();
    float S = 0.f, SS = 0.f;
    #pragma unroll
    for (int i = 0; i < 8; i++) { S += rs[i]; SS += rss[i]; }
    float mean = S * (1.f / DMODEL);
    float var  = SS * (1.f / DMODEL) - mean * mean;
    float rstd = rsqrtf(var + LN_EPS);
    const float4 gv = ((const float4*)g)[t];
    const float4 bv = ((const float4*)b)[t];
    float o0 = (v.x - mean) * rstd * gv.x + bv.x;
    float o1 = (v.y - mean) * rstd * gv.y + bv.y;
    float o2 = (v.z - mean) * rstd * gv.z + bv.z;
    float o3 = (v.w - mean) * rstd * gv.w + bv.w;
    __half2* ph = (__half2*)(ah + (size_t)row * DMODEL);
    ph[t*2]   = __floats2half2_rn(o0, o1);
    ph[t*2+1] = __floats2half2_rn(o2, o3);
}

// ---------------- fp32 -> fp16 convert (weights), 8 elems/thread ----------------
__global__ __launch_bounds__(256) void cvt16(const float* __restrict__ src,
                                             __half* __restrict__ dst) {
    size_t i = ((size_t)blockIdx.x * 256 + threadIdx.x) * 8;
    const float4 f0 = *(const float4*)(src + i);
    const float4 f1 = *(const float4*)(src + i + 4);
    __half2 h0 = __floats2half2_rn(f0.x, f0.y);
    __half2 h1 = __floats2half2_rn(f0.z, f0.w);
    __half2 h2 = __floats2half2_rn(f1.x, f1.y);
    __half2 h3 = __floats2half2_rn(f1.z, f1.w);
    uint4 ph;
    ph.x = *(uint32_t*)&h0; ph.y = *(uint32_t*)&h1;
    ph.z = *(uint32_t*)&h2; ph.w = *(uint32_t*)&h3;
    *(uint4*)(dst + i) = ph;
}

__global__ void pack_bias(const float* __restrict__ a, const float* __restrict__ b,
                          const float* __restrict__ c, float* __restrict__ out) {
    int i = blockIdx.x * 256 + threadIdx.x;
    float v = (i < 1024) ? a[i] : (i < 2048) ? b[i - 1024] : c[i - 2048];
    out[i] = v;
}

// ---------------- PTX helpers ----------------
#define CP16(sa, ga) asm volatile("cp.async.cg.shared.global [%0], [%1], 16;\n" :: "r"(sa), "l"(ga))
#define COMMIT() asm volatile("cp.async.commit_group;\n" ::)
#define LDMX4(r0,r1,r2,r3,addr) asm volatile( \
    "ldmatrix.sync.aligned.m8n8.x4.shared.b16 {%0,%1,%2,%3}, [%4];" \
    : "=r"(r0), "=r"(r1), "=r"(r2), "=r"(r3) : "r"(addr))
#define LDMX4T(r0,r1,r2,r3,addr) asm volatile( \
    "ldmatrix.sync.aligned.m8n8.x4.trans.shared.b16 {%0,%1,%2,%3}, [%4];" \
    : "=r"(r0), "=r"(r1), "=r"(r2), "=r"(r3) : "r"(addr))
#define MMA16816(d, a0,a1,a2,a3, b0,b1) asm volatile( \
    "mma.sync.aligned.m16n8k16.row.col.f32.f16.f16.f32 " \
    "{%0,%1,%2,%3}, {%4,%5,%6,%7}, {%8,%9}, {%0,%1,%2,%3};" \
    : "+f"(d[0]), "+f"(d[1]), "+f"(d[2]), "+f"(d[3]) \
    : "r"(a0), "r"(a1), "r"(a2), "r"(a3), "r"(b0), "r"(b1))

// ---------------- single-term fp16 GEMM (BK=64, double buffer) ----------------
#define GSTRIDE 72
#define TILE_H  (128 * GSTRIDE)
#define STAGE_H (2 * TILE_H)
#define GSMEM_BYTES (2 * STAGE_H * 2)

__device__ __forceinline__ void g_load_stage(uint32_t smBase, int stg,
                                             const __half* gA, const __half* gB,
                                             int K, int k0, int tid) {
    const uint32_t sb = smBase + (uint32_t)(stg * STAGE_H * 2);
    #pragma unroll
    for (int i = 0; i < 4; i++) {
        const int idx = tid + i * 256;
        const int r = idx >> 3, sg = (idx & 7) * 8;
        const uint32_t so = (uint32_t)((r * GSTRIDE + sg) << 1);
        const size_t go = (size_t)r * K + k0 + sg;
        CP16(sb + so,              gA + go);
        CP16(sb + TILE_H * 2 + so, gB + go);
    }
    COMMIT();
}

__global__ __launch_bounds__(256, 2) void hgemm1t(const __half* __restrict__ A,
                                                  const __half* __restrict__ B,
                                                  const float* __restrict__ bias,
                                                  const float* __restrict__ R,
                                                  float* __restrict__ C,
                                                  __half* __restrict__ Ch,
                                                  int M, int N, int K, int epi) {
    extern __shared__ __half sm16[];

    const int tid  = threadIdx.x;
    const int wid  = tid >> 5;
    const int lane = tid & 31;
    const int bm   = blockIdx.y * 128;
    const int bn   = blockIdx.x * 128;
    const int wm0  = (wid >> 2) * 64;
    const int wn0  = (wid & 3) * 32;

    float acc[4][4][4];
    #pragma unroll
    for (int i = 0; i < 4; i++)
        #pragma unroll
        for (int j = 0; j < 4; j++)
            #pragma unroll
            for (int t = 0; t < 4; t++) acc[i][j][t] = 0.f;

    const int nk = K >> 6;
    const uint32_t smBase = (uint32_t)__cvta_generic_to_shared(sm16);
    #define SADDR(stage, tile, row, col) (smBase + (((stage)*STAGE_H + (tile)*TILE_H + (row)*GSTRIDE + (col)) << 1))

    const __half* gA = A + (size_t)bm * K;
    const __half* gB = B + (size_t)bn * K;

    g_load_stage(smBase, 0, gA, gB, K, 0, tid);

    const int aRow  = (lane & 15);
    const int fBase = ((lane >> 4) << 3);

    for (int kt = 0; kt < nk; kt++) {
        const int buf = kt & 1;
        asm volatile("cp.async.wait_group 0;\n" ::);
        __syncthreads();
        if (kt + 1 < nk)
            g_load_stage(smBase, buf ^ 1, gA, gB, K, (kt + 1) << 6, tid);

        #pragma unroll
        for (int ks = 0; ks < 4; ks++) {
            const int fcol = ks * 16 + fBase;
            uint32_t bh[2][4];
            #pragma unroll
            for (int nt2 = 0; nt2 < 2; nt2++) {
                LDMX4(bh[nt2][0], bh[nt2][1], bh[nt2][2], bh[nt2][3],
                      SADDR(buf, 1, wn0 + nt2 * 16 + aRow, fcol));
            }
            #pragma unroll
            for (int mt = 0; mt < 4; mt++) {
                uint32_t a0, a1, a2, a3;
                LDMX4(a0, a1, a2, a3, SADDR(buf, 0, wm0 + mt * 16 + aRow, fcol));
                #pragma unroll
                for (int nt = 0; nt < 4; nt++)
                    MMA16816(acc[mt][nt], a0, a1, a2, a3,
                             bh[nt >> 1][nt & 1], bh[nt >> 1][(nt & 1) + 2]);
            }
        }
    }

    // ---- epilogue ----
    const int g  = lane >> 2;
    const int tg = lane & 3;
    #pragma unroll
    for (int mt = 0; mt < 4; mt++) {
        #pragma unroll
        for (int nt = 0; nt < 4; nt++) {
            const int col = bn + wn0 + nt * 8 + tg * 2;
            const float bx = bias[col], by = bias[col + 1];
            #pragma unroll
            for (int hh = 0; hh < 2; hh++) {
                const int row = bm + wm0 + mt * 16 + g + hh * 8;
                float v0 = acc[mt][nt][hh * 2 + 0] + bx;
                float v1 = acc[mt][nt][hh * 2 + 1] + by;
                if (epi == 4) {
                    v0 = 0.5f * v0 * (1.0f + erff(v0 * 0.7071067811865475f));
                    v1 = 0.5f * v1 * (1.0f + erff(v1 * 0.7071067811865475f));
                }
                if (epi == 2) {
                    const float2 rv = *(const float2*)&R[(size_t)row * N + col];
                    v0 += rv.x; v1 += rv.y;
                    float2 o; o.x = v0; o.y = v1;
                    *(float2*)&C[(size_t)row * N + col] = o;
                } else {
                    *(__half2*)&Ch[(size_t)row * N + col] = __floats2half2_rn(v0, v1);
                }
            }
        }
    }
}

// ---------------- tensor-core causal flash attention ----------------
// q-tile 128 (8 warps), key chunk 128, double-buffered K/V.
#define QS 72
#define ATTN_Q_OFF 0
#define ATTN_K_OFF (128 * QS)
#define ATTN_V_OFF (3 * 128 * QS)
#define ATTN_SMEM_BYTES (5 * 128 * QS * 2)   // 92160

__global__ __launch_bounds__(256) void attn_tc(const __half* __restrict__ QKVh,
                                               __half* __restrict__ Oh) {
    extern __shared__ __half asm16[];

    const int bh = blockIdx.y;
    const int b  = bh >> 4;
    const int h  = bh & 15;
    const int q0 = blockIdx.x * 128;
    const int tid  = threadIdx.x;
    const int wq   = tid >> 5;
    const int lane = tid & 31;
    const int g  = lane >> 2;
    const int tg = lane & 3;

    const __half* Qg = QKVh + ((size_t)b * SEQ + q0) * QKVW + h * HDIM;
    const __half* Kg = QKVh + (size_t)b * SEQ * QKVW + DMODEL + h * HDIM;
    const __half* Vg = Kg + DMODEL;

    const uint32_t qB = (uint32_t)__cvta_generic_to_shared(asm16) + ATTN_Q_OFF * 2;
    const uint32_t kB = (uint32_t)__cvta_generic_to_shared(asm16) + ATTN_K_OFF * 2;
    const uint32_t vB = (uint32_t)__cvta_generic_to_shared(asm16) + ATTN_V_OFF * 2;
    const uint32_t bufStride = 128 * QS * 2;

    // Q: 128 rows x 8 chunks; K/V chunk 0: 128 rows x 8 chunks each
    #pragma unroll
    for (int i = 0; i < 4; i++) {
        int idx = tid + i * 256;
        int r = idx >> 3, sg = (idx & 7) * 8;
        CP16(qB + (r * QS + sg) * 2, Qg + (size_t)r * QKVW + sg);
        CP16(kB + (r * QS + sg) * 2, Kg + (size_t)r * QKVW + sg);
        CP16(vB + (r * QS + sg) * 2, Vg + (size_t)r * QKVW + sg);
    }
    COMMIT();

    uint32_t Qa[4][4];
    float    o[8][4];
    #pragma unroll
    for (int i = 0; i < 8; i++)
        #pragma unroll
        for (int j = 0; j < 4; j++) o[i][j] = 0.f;
    float m0 = -1e30f, m1 = -1e30f, l0 = 0.f, l1 = 0.f;

    const int nchunks = (q0 >> 7) + 1;
    for (int it = 0; it < nchunks; it++) {
        const int buf = it & 1;
        if (it + 1 < nchunks) {
            const int c1 = (it + 1) << 7;
            #pragma unroll
            for (int i = 0; i < 4; i++) {
                int idx = tid + i * 256;
                int r = idx >> 3, sg = (idx & 7) * 8;
                CP16(kB + (buf ^ 1) * bufStride + (r * QS + sg) * 2, Kg + (size_t)(c1 + r) * QKVW + sg);
                CP16(vB + (buf ^ 1) * bufStride + (r * QS + sg) * 2, Vg + (size_t)(c1 + r) * QKVW + sg);
            }
            COMMIT();
            asm volatile("cp.async.wait_group 1;\n" ::);
        } else {
            asm volatile("cp.async.wait_group 0;\n" ::);
        }
        __syncthreads();

        if (it == 0) {
            #pragma unroll
            for (int kk = 0; kk < 4; kk++) {
                uint32_t addr = qB + ((wq * 16 + (lane & 15)) * QS + kk * 16 + ((lane >> 4) << 3)) * 2;
                LDMX4(Qa[kk][0], Qa[kk][1], Qa[kk][2], Qa[kk][3], addr);
            }
        }

        float s[16][4];
        #pragma unroll
        for (int i = 0; i < 16; i++)
            #pragma unroll
            for (int j = 0; j < 4; j++) s[i][j] = 0.f;

        #pragma unroll
        for (int kk = 0; kk < 4; kk++) {
            #pragma unroll
            for (int nt2 = 0; nt2 < 8; nt2++) {
                uint32_t r0, r1, r2, r3;
                uint32_t addr = kB + buf * bufStride +
                    ((nt2 * 16 + (lane & 15)) * QS + kk * 16 + ((lane >> 4) << 3)) * 2;
                LDMX4(r0, r1, r2, r3, addr);
                MMA16816(s[nt2 * 2],     Qa[kk][0], Qa[kk][1], Qa[kk][2], Qa[kk][3], r0, r2);
                MMA16816(s[nt2 * 2 + 1], Qa[kk][0], Qa[kk][1], Qa[kk][2], Qa[kk][3], r1, r3);
            }
        }

        #pragma unroll
        for (int nt = 0; nt < 16; nt++)
            #pragma unroll
            for (int j = 0; j < 4; j++) s[nt][j] *= 0.125f;

        if (it == nchunks - 1) {     // diagonal chunk (c0 == q0)
            const int row0a = wq * 16 + g;
            const int row1a = row0a + 8;
            #pragma unroll
            for (int nt = 0; nt < 16; nt++) {
                const int key = nt * 8 + 2 * tg;
                if (key     > row0a) s[nt][0] = -1e30f;
                if (key + 1 > row0a) s[nt][1] = -1e30f;
                if (key     > row1a) s[nt][2] = -1e30f;
                if (key + 1 > row1a) s[nt][3] = -1e30f;
            }
        }

        float mx0 = -1e30f, mx1 = -1e30f;
        #pragma unroll
        for (int nt = 0; nt < 16; nt++) {
            mx0 = fmaxf(mx0, fmaxf(s[nt][0], s[nt][1]));
            mx1 = fmaxf(mx1, fmaxf(s[nt][2], s[nt][3]));
        }
        mx0 = fmaxf(mx0, __shfl_xor_sync(0xffffffffu, mx0, 1));
        mx0 = fmaxf(mx0, __shfl_xor_sync(0xffffffffu, mx0, 2));
        mx1 = fmaxf(mx1, __shfl_xor_sync(0xffffffffu, mx1, 1));
        mx1 = fmaxf(mx1, __shfl_xor_sync(0xffffffffu, mx1, 2));
        const float mn0 = fmaxf(m0, mx0), mn1 = fmaxf(m1, mx1);
        const float cr0 = __expf(m0 - mn0), cr1 = __expf(m1 - mn1);
        float ps0 = 0.f, ps1 = 0.f;
        #pragma unroll
        for (int nt = 0; nt < 16; nt++) {
            s[nt][0] = __expf(s[nt][0] - mn0);
            s[nt][1] = __expf(s[nt][1] - mn0);
            s[nt][2] = __expf(s[nt][2] - mn1);
            s[nt][3] = __expf(s[nt][3] - mn1);
            ps0 += s[nt][0] + s[nt][1];
            ps1 += s[nt][2] + s[nt][3];
        }
        ps0 += __shfl_xor_sync(0xffffffffu, ps0, 1);
        ps0 += __shfl_xor_sync(0xffffffffu, ps0, 2);
        ps1 += __shfl_xor_sync(0xffffffffu, ps1, 1);
        ps1 += __shfl_xor_sync(0xffffffffu, ps1, 2);
        l0 = l0 * cr0 + ps0;
        l1 = l1 * cr1 + ps1;
        m0 = mn0; m1 = mn1;
        #pragma unroll
        for (int nd = 0; nd < 8; nd++) {
            o[nd][0] *= cr0; o[nd][1] *= cr0;
            o[nd][2] *= cr1; o[nd][3] *= cr1;
        }

        #pragma unroll
        for (int kk = 0; kk < 8; kk++) {
            __half2 t0 = __floats2half2_rn(s[2*kk][0],   s[2*kk][1]);
            __half2 t1 = __floats2half2_rn(s[2*kk][2],   s[2*kk][3]);
            __half2 t2 = __floats2half2_rn(s[2*kk+1][0], s[2*kk+1][1]);
            __half2 t3 = __floats2half2_rn(s[2*kk+1][2], s[2*kk+1][3]);
            uint32_t pa0 = *(uint32_t*)&t0, pa1 = *(uint32_t*)&t1;
            uint32_t pa2 = *(uint32_t*)&t2, pa3 = *(uint32_t*)&t3;
            #pragma unroll
            for (int nd2 = 0; nd2 < 4; nd2++) {
                uint32_t r0, r1, r2, r3;
                uint32_t addr = vB + buf * bufStride +
                    ((kk * 16 + (lane & 15)) * QS + nd2 * 16 + ((lane >> 4) << 3)) * 2;
                LDMX4T(r0, r1, r2, r3, addr);
                MMA16816(o[nd2 * 2],     pa0, pa1, pa2, pa3, r0, r1);
                MMA16816(o[nd2 * 2 + 1], pa0, pa1, pa2, pa3, r2, r3);
            }
        }
        __syncthreads();
    }

    const float inv0 = 1.f / l0, inv1 = 1.f / l1;
    const int row0 = q0 + wq * 16 + g;
    const size_t ob0 = ((size_t)b * SEQ + row0) * DMODEL + h * HDIM;
    const size_t ob1 = ob0 + 8 * DMODEL;
    #pragma unroll
    for (int nd = 0; nd < 8; nd++) {
        const int d = nd * 8 + 2 * tg;
        *(__half2*)&Oh[ob0 + d] = __floats2half2_rn(o[nd][0] * inv0, o[nd][1] * inv0);
        *(__half2*)&Oh[ob1 + d] = __floats2half2_rn(o[nd][2] * inv1, o[nd][3] * inv1);
    }
}

// ---------------- launcher ----------------
extern "C" void kernel_launch(void* const* d_in, const int* in_sizes, int n_in,
                              void* d_out, int out_size) {
    const float* x     = (const float*)d_in[0];
    const float* Wq    = (const float*)d_in[2];
    const float* bq    = (const float*)d_in[3];
    const float* Wk    = (const float*)d_in[4];
    const float* bk    = (const float*)d_in[5];
    const float* Wv    = (const float*)d_in[6];
    const float* bv    = (const float*)d_in[7];
    const float* Wo    = (const float*)d_in[8];
    const float* bo    = (const float*)d_in[9];
    const float* W1    = (const float*)d_in[10];
    const float* b1    = (const float*)d_in[11];
    const float* W2    = (const float*)d_in[12];
    const float* b2    = (const float*)d_in[13];
    const float* g1    = (const float*)d_in[14];
    const float* beta1 = (const float*)d_in[15];
    const float* g2    = (const float*)d_in[16];
    const float* beta2 = (const float*)d_in[17];
    float* out = (float*)d_out;

    float *x2, *bqkv;
    __half *qkvh, *ah, *hh, *wh;
    cudaGetSymbolAddress((void**)&x2,   g_x2);
    cudaGetSymbolAddress((void**)&bqkv, g_bqkv);
    cudaGetSymbolAddress((void**)&qkvh, g_qkvh);
    cudaGetSymbolAddress((void**)&ah,   g_ah);
    cudaGetSymbolAddress((void**)&hh,   g_hh);
    cudaGetSymbolAddress((void**)&wh,   g_wh);

    static cudaStream_t s2 = nullptr;
    static cudaEvent_t eF, e1, e2, e3, e4;
    static bool init_done = false;
    if (!init_done) {
        cudaFuncSetAttribute(hgemm1t, cudaFuncAttributeMaxDynamicSharedMemorySize, GSMEM_BYTES);
        cudaFuncSetAttribute(attn_tc, cudaFuncAttributeMaxDynamicSharedMemorySize, ATTN_SMEM_BYTES);
        cudaStreamCreateWithFlags(&s2, cudaStreamNonBlocking);
        cudaEventCreateWithFlags(&eF, cudaEventDisableTiming);
        cudaEventCreateWithFlags(&e1, cudaEventDisableTiming);
        cudaEventCreateWithFlags(&e2, cudaEventDisableTiming);
        cudaEventCreateWithFlags(&e3, cudaEventDisableTiming);
        cudaEventCreateWithFlags(&e4, cudaEventDisableTiming);
        init_done = true;
    }

    const int M = MROWS, D = DMODEL, F = FFDIM;
    const size_t DD = (size_t)D * D;   // 1M elems
    __half* wqkv = wh;                 // [0, 3DD)
    __half* wo16 = wh + 3 * DD;        // [3DD, 4DD)
    __half* w116 = wh + 4 * DD;        // [4DD, 8DD)
    __half* w216 = wh + 8 * DD;        // [8DD, 12DD)

    // ---- fork side stream for weight conversions ----
    cudaEventRecord(eF, 0);
    cudaStreamWaitEvent(s2, eF, 0);
    cvt16<<<(int)(DD / 8) / 256, 256, 0, s2>>>(Wq, wqkv);
    cvt16<<<(int)(DD / 8) / 256, 256, 0, s2>>>(Wk, wqkv + DD);
    cvt16<<<(int)(DD / 8) / 256, 256, 0, s2>>>(Wv, wqkv + 2 * DD);
    pack_bias<<<QKVW / 256, 256, 0, s2>>>(bq, bk, bv, bqkv);
    cudaEventRecord(e1, s2);
    cvt16<<<(int)(DD / 8) / 256, 256, 0, s2>>>(Wo, wo16);
    cudaEventRecord(e2, s2);
    cvt16<<<(int)((size_t)F * D / 8) / 256, 256, 0, s2>>>(W1, w116);
    cudaEventRecord(e3, s2);
    cvt16<<<(int)((size_t)D * F / 8) / 256, 256, 0, s2>>>(W2, w216);
    cudaEventRecord(e4, s2);

    // ---- main stream ----
    // LN1 -> fp16
    ln_h16<<<M, 256>>>(x, g1, beta1, ah);

    // fused QKV GEMM -> fp16 output (N = 3072)
    cudaStreamWaitEvent(0, e1, 0);
    dim3 gQKV(QKVW / 128, M / 128);
    hgemm1t<<<gQKV, 256, GSMEM_BYTES>>>(ah, wqkv, bqkv, nullptr,
                                        nullptr, qkvh, M, QKVW, D, 3);

    // tensor-core causal attention -> ctx fp16
    dim3 gA(SEQ / 128, BSZ * NHEADS);
    attn_tc<<<gA, 256, ATTN_SMEM_BYTES>>>(qkvh, ah);

    // output projection + residual -> x2 (fp32)
    cudaStreamWaitEvent(0, e2, 0);
    dim3 gD(D / 128, M / 128);
    hgemm1t<<<gD, 256, GSMEM_BYTES>>>(ah, wo16, bo, x,
                                      x2, nullptr, M, D, D, 2);

    // LN2 -> fp16
    ln_h16<<<M, 256>>>(x2, g2, beta2, ah);

    // FFN1 (GELU) -> hidden fp16 (N = 4096)
    cudaStreamWaitEvent(0, e3, 0);
    dim3 gF1(F / 128, M / 128);
    hgemm1t<<<gF1, 256, GSMEM_BYTES>>>(ah, w116, b1, nullptr,
                                       nullptr, hh, M, F, D, 4);

    // FFN2 + residual -> out (fp32), K = 4096
    cudaStreamWaitEvent(0, e4, 0);
    hgemm1t<<<gD, 256, GSMEM_BYTES>>>(hh, w216, b2, x2,
                                      out, nullptr, M, D, F, 2);
}